// round 1
// baseline (speedup 1.0000x reference)
#include <cuda_runtime.h>
#include <math.h>

#define E_DIM   1024
#define N_HEAD  16
#define HD      64
#define T_LEN   1024
#define N_LAYER 6
#define VOCAB   32000
#define BATCH   2
#define MTOK    (BATCH * T_LEN)     /* 2048 */
#define FF      (4 * E_DIM)         /* 4096 */

/* ---------------- scratch (static device globals; no allocations) -------- */
__device__ float g_x [MTOK * E_DIM];
__device__ float g_y [MTOK * E_DIM];
__device__ float g_q [N_HEAD * MTOK * HD];
__device__ float g_k [N_HEAD * MTOK * HD];
__device__ float g_v [N_HEAD * MTOK * HD];
__device__ float g_o [N_HEAD * MTOK * HD];
__device__ float g_o2[MTOK * E_DIM];
__device__ float g_h [MTOK * FF];
__device__ float g_nll[MTOK];
__device__ float g_logits_scratch[(size_t)MTOK * VOCAB];

/* ---------------- embedding gather --------------------------------------- */
__global__ void embed_kernel(const int* __restrict__ idx,
                             const float* __restrict__ emb,
                             float* __restrict__ x) {
    int i = blockIdx.x * blockDim.x + threadIdx.x;
    if (i < MTOK * E_DIM) {
        int m = i >> 10;
        int e = i & 1023;
        x[i] = emb[(size_t)idx[m] * E_DIM + e];
    }
}

/* ---------------- layernorm (one block per token row) -------------------- */
__global__ __launch_bounds__(256)
void ln_kernel(const float* __restrict__ x, const float* __restrict__ g,
               const float* __restrict__ b, float* __restrict__ y) {
    int m = blockIdx.x;
    int tid = threadIdx.x;
    __shared__ float r1[256];
    __shared__ float r2[256];
    const float4* xr = (const float4*)(x + (size_t)m * E_DIM);
    float4 v = xr[tid];
    r1[tid] = v.x + v.y + v.z + v.w;
    r2[tid] = v.x*v.x + v.y*v.y + v.z*v.z + v.w*v.w;
    __syncthreads();
    for (int s = 128; s > 0; s >>= 1) {
        if (tid < s) { r1[tid] += r1[tid + s]; r2[tid] += r2[tid + s]; }
        __syncthreads();
    }
    float mean = r1[0] * (1.0f / E_DIM);
    float var  = r2[0] * (1.0f / E_DIM) - mean * mean;
    float rstd = rsqrtf(var + 1e-5f);
    float4 gg = ((const float4*)g)[tid];
    float4 bb = ((const float4*)b)[tid];
    float4 o;
    o.x = (v.x - mean) * rstd * gg.x + bb.x;
    o.y = (v.y - mean) * rstd * gg.y + bb.y;
    o.z = (v.z - mean) * rstd * gg.z + bb.z;
    o.w = (v.w - mean) * rstd * gg.w + bb.w;
    ((float4*)(y + (size_t)m * E_DIM))[tid] = o;
}

/* ---------------- tiled SGEMM: C = A*B (+bias)(+res)(relu) --------------- */
/* BM=BN=64, BK=16, 256 threads, 4x4 microtile per thread                    */
template<bool RELU>
__global__ __launch_bounds__(256)
void sgemm_k(const float* __restrict__ A, int lda, long strideA,
             const float* __restrict__ B, int ldb, long strideB,
             float* __restrict__ C, int ldc, long strideC,
             const float* __restrict__ bias,
             const float* __restrict__ res, int ldres,
             int M, int N, int K) {
    int z = blockIdx.z;
    A += (size_t)z * strideA;
    B += (size_t)z * strideB;
    C += (size_t)z * strideC;

    int bm = blockIdx.y * 64;
    int bn = blockIdx.x * 64;
    int tid = threadIdx.x;
    int tx = tid & 15;       /* col group */
    int ty = tid >> 4;       /* row group */

    __shared__ __align__(16) float As[16][64];
    __shared__ __align__(16) float Bs[16][64];

    float acc[4][4] = {};

    int arow = tid >> 2;            /* 0..63 */
    int acol = (tid & 3) * 4;       /* 0,4,8,12 */
    int brow = tid >> 4;            /* 0..15 */
    int bcol = (tid & 15) * 4;      /* 0..60 */

    for (int k0 = 0; k0 < K; k0 += 16) {
        float4 av = *(const float4*)(A + (size_t)(bm + arow) * lda + k0 + acol);
        As[acol + 0][arow] = av.x;
        As[acol + 1][arow] = av.y;
        As[acol + 2][arow] = av.z;
        As[acol + 3][arow] = av.w;
        *(float4*)(&Bs[brow][bcol]) =
            *(const float4*)(B + (size_t)(k0 + brow) * ldb + bn + bcol);
        __syncthreads();
        #pragma unroll
        for (int kk = 0; kk < 16; kk++) {
            float4 a = *(float4*)(&As[kk][ty * 4]);
            float4 b = *(float4*)(&Bs[kk][tx * 4]);
            acc[0][0] += a.x * b.x; acc[0][1] += a.x * b.y; acc[0][2] += a.x * b.z; acc[0][3] += a.x * b.w;
            acc[1][0] += a.y * b.x; acc[1][1] += a.y * b.y; acc[1][2] += a.y * b.z; acc[1][3] += a.y * b.w;
            acc[2][0] += a.z * b.x; acc[2][1] += a.z * b.y; acc[2][2] += a.z * b.z; acc[2][3] += a.z * b.w;
            acc[3][0] += a.w * b.x; acc[3][1] += a.w * b.y; acc[3][2] += a.w * b.z; acc[3][3] += a.w * b.w;
        }
        __syncthreads();
    }

    int col = bn + tx * 4;
    #pragma unroll
    for (int i = 0; i < 4; i++) {
        int row = bm + ty * 4 + i;
        float4 o = make_float4(acc[i][0], acc[i][1], acc[i][2], acc[i][3]);
        if (bias) {
            o.x += bias[col]; o.y += bias[col + 1]; o.z += bias[col + 2]; o.w += bias[col + 3];
        }
        if (res) {
            float4 r = *(const float4*)(res + (size_t)row * ldres + col);
            o.x += r.x; o.y += r.y; o.z += r.z; o.w += r.w;
        }
        if (RELU) {
            o.x = fmaxf(o.x, 0.f); o.y = fmaxf(o.y, 0.f);
            o.z = fmaxf(o.z, 0.f); o.w = fmaxf(o.w, 0.f);
        }
        *(float4*)(C + (size_t)row * ldc + col) = o;
    }
}

/* ---------------- RoPE (interleaved pairs), layout [H][M][HD] ------------ */
__global__ void rope_kernel(float* __restrict__ x) {
    int i = blockIdx.x * blockDim.x + threadIdx.x;   /* H*MTOK*(HD/2) = 1M */
    if (i >= N_HEAD * MTOK * (HD / 2)) return;
    int p = i & 31;
    int m = (i >> 5) & (MTOK - 1);
    int h = i >> 16;
    int t = m & (T_LEN - 1);
    float invf = powf(10000.f, -(float)(2 * p) / (float)HD);
    float ang = (float)t * invf;
    float sn, cs;
    sincosf(ang, &sn, &cs);
    float* base = x + ((size_t)(h * MTOK + m) << 6) + 2 * p;
    float x0 = base[0], x1 = base[1];
    base[0] = x0 * cs - x1 * sn;
    base[1] = x0 * sn + x1 * cs;
}

/* ---------------- fused causal attention, one block per (b,h,t) ---------- */
__global__ __launch_bounds__(256)
void attn_kernel(const float* __restrict__ q, const float* __restrict__ k,
                 const float* __restrict__ v, float* __restrict__ out) {
    int t  = blockIdx.x;
    int b  = blockIdx.y >> 4;
    int h  = blockIdx.y & 15;
    int base = h * MTOK + b * T_LEN;                 /* row offset into [H][M][HD] */
    const float* qr = q + ((size_t)(base + t) << 6);
    const float* kb = k + ((size_t)base << 6);
    const float* vb = v + ((size_t)base << 6);

    __shared__ __align__(16) float qs[HD];
    __shared__ float sc[T_LEN];
    __shared__ float red[256];
    int tid = threadIdx.x;

    if (tid < 16) ((float4*)qs)[tid] = ((const float4*)qr)[tid];
    __syncthreads();

    const float scale = 0.03125f;                    /* n_embd^-0.5 = 1/32 */
    for (int s = tid; s <= t; s += 256) {
        const float4* kr = (const float4*)(kb + ((size_t)s << 6));
        float acc = 0.f;
        #pragma unroll
        for (int i = 0; i < 16; i++) {
            float4 kv = kr[i];
            float4 qv = ((float4*)qs)[i];
            acc += kv.x*qv.x + kv.y*qv.y + kv.z*qv.z + kv.w*qv.w;
        }
        sc[s] = acc * scale;
    }
    __syncthreads();

    /* max */
    float mval = -1e30f;
    for (int s = tid; s <= t; s += 256) mval = fmaxf(mval, sc[s]);
    red[tid] = mval;
    __syncthreads();
    for (int s = 128; s > 0; s >>= 1) {
        if (tid < s) red[tid] = fmaxf(red[tid], red[tid + s]);
        __syncthreads();
    }
    float mx = red[0];
    __syncthreads();

    /* exp + sum */
    float sum = 0.f;
    for (int s = tid; s <= t; s += 256) {
        float e = __expf(sc[s] - mx);
        sc[s] = e;
        sum += e;
    }
    red[tid] = sum;
    __syncthreads();
    for (int s = 128; s > 0; s >>= 1) {
        if (tid < s) red[tid] += red[tid + s];
        __syncthreads();
    }
    float inv = 1.f / red[0];
    __syncthreads();

    /* AV: 4 s-groups x 64 dims */
    int d  = tid & 63;
    int sg = tid >> 6;
    float acc = 0.f;
    for (int s = sg; s <= t; s += 4)
        acc += sc[s] * vb[((size_t)s << 6) + d];
    red[tid] = acc;
    __syncthreads();
    if (sg == 0)
        out[((size_t)(base + t) << 6) + d] =
            (red[d] + red[64 + d] + red[128 + d] + red[192 + d]) * inv;
}

/* ---------------- repack [H][M][HD] -> [M][H*HD] -------------------------- */
__global__ void repack_kernel(const float* __restrict__ o, float* __restrict__ o2) {
    int i = blockIdx.x * blockDim.x + threadIdx.x;
    if (i < MTOK * E_DIM) {
        int m = i >> 10;
        int j = i & 1023;
        int h = j >> 6;
        int d = j & 63;
        o2[i] = o[((size_t)(h * MTOK + m) << 6) + d];
    }
}

/* ---------------- per-row NLL over vocab ---------------------------------- */
__global__ __launch_bounds__(256)
void nll_kernel(const float* __restrict__ logits, const int* __restrict__ tgt,
                float* __restrict__ nll) {
    int m = blockIdx.x;
    int tid = threadIdx.x;
    const float* lr = logits + (size_t)m * VOCAB;
    __shared__ float red[256];
    float mx = -1e30f;
    for (int n = tid; n < VOCAB; n += 256) mx = fmaxf(mx, lr[n]);
    red[tid] = mx;
    __syncthreads();
    for (int s = 128; s > 0; s >>= 1) {
        if (tid < s) red[tid] = fmaxf(red[tid], red[tid + s]);
        __syncthreads();
    }
    mx = red[0];
    __syncthreads();
    float sum = 0.f;
    for (int n = tid; n < VOCAB; n += 256) sum += __expf(lr[n] - mx);
    red[tid] = sum;
    __syncthreads();
    for (int s = 128; s > 0; s >>= 1) {
        if (tid < s) red[tid] += red[tid + s];
        __syncthreads();
    }
    if (tid == 0)
        nll[m] = (logf(red[0]) + mx) - lr[tgt[m]];
}

__global__ __launch_bounds__(256)
void loss_reduce_kernel(const float* __restrict__ nll, float* __restrict__ out) {
    __shared__ float red[256];
    int tid = threadIdx.x;
    float s = 0.f;
    for (int i = tid; i < MTOK; i += 256) s += nll[i];
    red[tid] = s;
    __syncthreads();
    for (int k = 128; k > 0; k >>= 1) {
        if (tid < k) red[tid] += red[tid + k];
        __syncthreads();
    }
    if (tid == 0) out[0] = red[0] * (1.0f / MTOK);
}

/* ---------------- host orchestration -------------------------------------- */
extern "C" void kernel_launch(void* const* d_in, const int* in_sizes, int n_in,
                              void* d_out, int out_size) {
    const int*   idx   = (const int*)  d_in[0];
    const int*   tgt   = (const int*)  d_in[1];
    const float* emb   = (const float*)d_in[2];
    const float* wq    = (const float*)d_in[3];
    const float* wk    = (const float*)d_in[4];
    const float* wv    = (const float*)d_in[5];
    const float* wproj = (const float*)d_in[6];
    const float* bproj = (const float*)d_in[7];
    const float* w1    = (const float*)d_in[8];
    const float* b1    = (const float*)d_in[9];
    const float* w2    = (const float*)d_in[10];
    const float* b2    = (const float*)d_in[11];
    const float* ln1g  = (const float*)d_in[12];
    const float* ln1b  = (const float*)d_in[13];
    const float* ln2g  = (const float*)d_in[14];
    const float* ln2b  = (const float*)d_in[15];
    const float* lm_w  = (const float*)d_in[16];
    const float* lm_b  = (const float*)d_in[17];

    float *x, *y, *q, *k, *v, *o, *o2, *hbuf, *nll, *lscr;
    cudaGetSymbolAddress((void**)&x,    g_x);
    cudaGetSymbolAddress((void**)&y,    g_y);
    cudaGetSymbolAddress((void**)&q,    g_q);
    cudaGetSymbolAddress((void**)&k,    g_k);
    cudaGetSymbolAddress((void**)&v,    g_v);
    cudaGetSymbolAddress((void**)&o,    g_o);
    cudaGetSymbolAddress((void**)&o2,   g_o2);
    cudaGetSymbolAddress((void**)&hbuf, g_h);
    cudaGetSymbolAddress((void**)&nll,  g_nll);
    cudaGetSymbolAddress((void**)&lscr, g_logits_scratch);

    const long BTV = (long)MTOK * VOCAB;
    float* logits = ((long)out_size >= BTV) ? (float*)d_out : lscr;

    embed_kernel<<<(MTOK * E_DIM + 255) / 256, 256>>>(idx, emb, x);

    const long HED = (long)N_HEAD * E_DIM * HD;      /* per-layer qkv weight */

    for (int l = 0; l < N_LAYER; l++) {
        ln_kernel<<<MTOK, 256>>>(x, ln1g + (size_t)l * E_DIM, ln1b + (size_t)l * E_DIM, y);

        dim3 gqkv(1, MTOK / 64, N_HEAD);
        sgemm_k<false><<<gqkv, 256>>>(y, E_DIM, 0,
                                      wq + (size_t)l * HED, HD, (long)E_DIM * HD,
                                      q, HD, (long)MTOK * HD,
                                      nullptr, nullptr, 0, MTOK, HD, E_DIM);
        sgemm_k<false><<<gqkv, 256>>>(y, E_DIM, 0,
                                      wk + (size_t)l * HED, HD, (long)E_DIM * HD,
                                      k, HD, (long)MTOK * HD,
                                      nullptr, nullptr, 0, MTOK, HD, E_DIM);
        sgemm_k<false><<<gqkv, 256>>>(y, E_DIM, 0,
                                      wv + (size_t)l * HED, HD, (long)E_DIM * HD,
                                      v, HD, (long)MTOK * HD,
                                      nullptr, nullptr, 0, MTOK, HD, E_DIM);

        int nrope = N_HEAD * MTOK * (HD / 2);
        rope_kernel<<<(nrope + 255) / 256, 256>>>(q);
        rope_kernel<<<(nrope + 255) / 256, 256>>>(k);

        attn_kernel<<<dim3(T_LEN, BATCH * N_HEAD), 256>>>(q, k, v, o);

        repack_kernel<<<(MTOK * E_DIM + 255) / 256, 256>>>(o, o2);

        sgemm_k<false><<<dim3(E_DIM / 64, MTOK / 64, 1), 256>>>(
            o2, E_DIM, 0,
            wproj + (size_t)l * E_DIM * E_DIM, E_DIM, 0,
            x, E_DIM, 0,
            bproj + (size_t)l * E_DIM, x, E_DIM, MTOK, E_DIM, E_DIM);

        ln_kernel<<<MTOK, 256>>>(x, ln2g + (size_t)l * E_DIM, ln2b + (size_t)l * E_DIM, y);

        sgemm_k<true><<<dim3(FF / 64, MTOK / 64, 1), 256>>>(
            y, E_DIM, 0,
            w1 + (size_t)l * E_DIM * FF, FF, 0,
            hbuf, FF, 0,
            b1 + (size_t)l * FF, nullptr, 0, MTOK, FF, E_DIM);

        sgemm_k<false><<<dim3(E_DIM / 64, MTOK / 64, 1), 256>>>(
            hbuf, FF, 0,
            w2 + (size_t)l * FF * E_DIM, E_DIM, 0,
            x, E_DIM, 0,
            b2 + (size_t)l * E_DIM, x, E_DIM, MTOK, E_DIM, FF);
    }

    sgemm_k<false><<<dim3(VOCAB / 64, MTOK / 64, 1), 256>>>(
        x, E_DIM, 0,
        lm_w, VOCAB, 0,
        logits, VOCAB, 0,
        lm_b, nullptr, 0, MTOK, VOCAB, E_DIM);

    nll_kernel<<<MTOK, 256>>>(logits, tgt, nll);

    if ((long)out_size == BTV + 1) {
        loss_reduce_kernel<<<1, 256>>>(nll, (float*)d_out + BTV);
    } else if ((long)out_size < BTV) {
        /* output is just the scalar loss */
        loss_reduce_kernel<<<1, 256>>>(nll, (float*)d_out);
    }
    /* if out_size == BTV exactly, logits already in d_out; nothing else */
}

// round 3
// speedup vs baseline: 1.5868x; 1.5868x over previous
#include <cuda_runtime.h>
#include <cuda_bf16.h>
#include <math.h>
#include <cstdint>

#define E_DIM   1024
#define N_HEAD  16
#define HD      64
#define T_LEN   1024
#define N_LAYER 6
#define VOCAB   32000
#define BATCH   2
#define MTOK    (BATCH * T_LEN)     /* 2048 */
#define FF      (4 * E_DIM)         /* 4096 */

/* ================= scratch =============================================== */
__device__ float g_x   [MTOK * E_DIM];
__device__ __nv_bfloat16 g_yh[MTOK * E_DIM];
__device__ __nv_bfloat16 g_yl[MTOK * E_DIM];
__device__ float g_qkv [MTOK * 3 * E_DIM];
__device__ __nv_bfloat16 g_oh[MTOK * E_DIM];
__device__ __nv_bfloat16 g_ol[MTOK * E_DIM];
__device__ __nv_bfloat16 g_hh[(size_t)MTOK * FF];
__device__ __nv_bfloat16 g_hl[(size_t)MTOK * FF];
__device__ float g_nllv[MTOK];
__device__ float g_logits_scratch[(size_t)MTOK * VOCAB];
/* transposed/split weights [N][K] bf16 */
__device__ __nv_bfloat16 g_qkvT_h[(size_t)N_LAYER * 3 * E_DIM * E_DIM];
__device__ __nv_bfloat16 g_qkvT_l[(size_t)N_LAYER * 3 * E_DIM * E_DIM];
__device__ __nv_bfloat16 g_projT_h[(size_t)N_LAYER * E_DIM * E_DIM];
__device__ __nv_bfloat16 g_projT_l[(size_t)N_LAYER * E_DIM * E_DIM];
__device__ __nv_bfloat16 g_w1T_h[(size_t)N_LAYER * FF * E_DIM];
__device__ __nv_bfloat16 g_w1T_l[(size_t)N_LAYER * FF * E_DIM];
__device__ __nv_bfloat16 g_w2T_h[(size_t)N_LAYER * E_DIM * FF];
__device__ __nv_bfloat16 g_w2T_l[(size_t)N_LAYER * E_DIM * FF];
__device__ __nv_bfloat16 g_lmT_h[(size_t)VOCAB * E_DIM];
__device__ __nv_bfloat16 g_lmT_l[(size_t)VOCAB * E_DIM];

/* ================= small PTX wrappers (base ISA only) ==================== */
__device__ __forceinline__ uint32_t smem_u32(const void* p) {
    uint32_t a;
    asm("{ .reg .u64 t; cvta.to.shared.u64 t, %1; cvt.u32.u64 %0, t; }" : "=r"(a) : "l"(p));
    return a;
}
__device__ __forceinline__ void cp16(uint32_t s, const void* g) {
    asm volatile("cp.async.cg.shared.global [%0], [%1], 16;" :: "r"(s), "l"(g));
}
__device__ __forceinline__ void cp_commit() { asm volatile("cp.async.commit_group;"); }
template<int N> __device__ __forceinline__ void cp_wait() {
    asm volatile("cp.async.wait_group %0;" :: "n"(N));
}
__device__ __forceinline__ void ldmA(uint32_t* r, uint32_t a) {
    asm volatile("ldmatrix.sync.aligned.m8n8.x4.shared.b16 {%0,%1,%2,%3}, [%4];"
                 : "=r"(r[0]), "=r"(r[1]), "=r"(r[2]), "=r"(r[3]) : "r"(a));
}
__device__ __forceinline__ void ldmB(uint32_t* r, uint32_t a) {
    asm volatile("ldmatrix.sync.aligned.m8n8.x2.shared.b16 {%0,%1}, [%2];"
                 : "=r"(r[0]), "=r"(r[1]) : "r"(a));
}
__device__ __forceinline__ void mma16816(float* c, const uint32_t* a, const uint32_t* b) {
    asm volatile("mma.sync.aligned.m16n8k16.row.col.f32.bf16.bf16.f32 "
                 "{%0,%1,%2,%3}, {%4,%5,%6,%7}, {%8,%9}, {%0,%1,%2,%3};"
                 : "+f"(c[0]), "+f"(c[1]), "+f"(c[2]), "+f"(c[3])
                 : "r"(a[0]), "r"(a[1]), "r"(a[2]), "r"(a[3]), "r"(b[0]), "r"(b[1]));
}

/* ================= HMMA GEMM ============================================= */
/* C[M,N] = (Ah+Al)[M,K] * (Bh+Bl)[N,K]^T   (3-MMA split-bf16, fp32 acc)     */
/* Block: 128x128, BK=32, 256 threads, 8 warps (2m x 4n), warp tile 64x32    */
#define ROWB   80                       /* padded smem row bytes (32 bf16 + pad) */
#define TILEB  (128 * ROWB)             /* 10240 per operand tile */
#define STAGEB (4 * TILEB)              /* Ah Al Bh Bl */
#define SMTOT  (2 * STAGEB)             /* 81920 */

template<bool RELU, bool SPLIT>
__global__ __launch_bounds__(256)
void mma_gemm(const __nv_bfloat16* __restrict__ Ah, const __nv_bfloat16* __restrict__ Al,
              const __nv_bfloat16* __restrict__ Bh, const __nv_bfloat16* __restrict__ Bl,
              int K, int N,
              float* __restrict__ C,
              __nv_bfloat16* __restrict__ Oh, __nv_bfloat16* __restrict__ Ol,
              const float* __restrict__ bias, const float* __restrict__ res) {
    extern __shared__ char smem[];
    const uint32_t sb = smem_u32(smem);
    const int tid = threadIdx.x;
    const int lane = tid & 31;
    const int wid = tid >> 5;
    const int warp_m = wid & 1;         /* 0..1 */
    const int warp_n = wid >> 1;        /* 0..3 */
    const size_t bm = (size_t)blockIdx.y * 128;
    const size_t bn = (size_t)blockIdx.x * 128;

    float acc[4][4][4];
    #pragma unroll
    for (int i = 0; i < 4; i++)
        #pragma unroll
        for (int j = 0; j < 4; j++)
            #pragma unroll
            for (int q = 0; q < 4; q++) acc[i][j][q] = 0.f;

    const int nc = K >> 5;

    /* loader: 2048 16B chunks per stage, 8 per thread */
    auto load_stage = [&](int c, int s) {
        const int k0 = c << 5;
        const uint32_t sbase = sb + s * STAGEB;
        #pragma unroll
        for (int t = 0; t < 8; t++) {
            int idx = tid + (t << 8);
            int tile = idx >> 9;                 /* 0 Ah, 1 Al, 2 Bh, 3 Bl */
            int r    = (idx >> 2) & 127;
            int cch  = idx & 3;
            const __nv_bfloat16* base = (tile == 0) ? Ah : (tile == 1) ? Al
                                      : (tile == 2) ? Bh : Bl;
            size_t grow = ((tile < 2) ? bm : bn) + r;
            const __nv_bfloat16* g = base + grow * (size_t)K + k0 + cch * 8;
            cp16(sbase + tile * TILEB + r * ROWB + cch * 16, g);
        }
        cp_commit();
    };

    load_stage(0, 0);

    const uint32_t aRowOff = (uint32_t)((warp_m * 64 + (lane & 15)) * ROWB + ((lane >> 4) << 4));
    const uint32_t bRowOff = (uint32_t)((warp_n * 32 + (lane & 7)) * ROWB + (((lane >> 3) & 1) << 4));

    for (int c = 0; c < nc; c++) {
        if (c + 1 < nc) { load_stage(c + 1, (c + 1) & 1); cp_wait<1>(); }
        else            { cp_wait<0>(); }
        __syncthreads();

        const uint32_t st = sb + (c & 1) * STAGEB;
        const uint32_t aH = st + aRowOff;
        const uint32_t aL = st + TILEB + aRowOff;
        const uint32_t bH = st + 2 * TILEB + bRowOff;
        const uint32_t bL = st + 3 * TILEB + bRowOff;

        #pragma unroll
        for (int kk = 0; kk < 2; kk++) {
            const uint32_t kb = kk * 32;
            uint32_t ah[4][4], al[4][4], bh[4][2], bl[4][2];
            #pragma unroll
            for (int mt = 0; mt < 4; mt++) {
                ldmA(ah[mt], aH + mt * (16 * ROWB) + kb);
                ldmA(al[mt], aL + mt * (16 * ROWB) + kb);
            }
            #pragma unroll
            for (int nt = 0; nt < 4; nt++) {
                ldmB(bh[nt], bH + nt * (8 * ROWB) + kb);
                ldmB(bl[nt], bL + nt * (8 * ROWB) + kb);
            }
            #pragma unroll
            for (int mt = 0; mt < 4; mt++)
                #pragma unroll
                for (int nt = 0; nt < 4; nt++) {
                    mma16816(acc[mt][nt], ah[mt], bh[nt]);
                    mma16816(acc[mt][nt], ah[mt], bl[nt]);
                    mma16816(acc[mt][nt], al[mt], bh[nt]);
                }
        }
        __syncthreads();
    }

    /* epilogue: thread holds (r0,col),(r0,col+1),(r0+8,col),(r0+8,col+1) per tile */
    #pragma unroll
    for (int mt = 0; mt < 4; mt++) {
        #pragma unroll
        for (int nt = 0; nt < 4; nt++) {
            size_t col = bn + warp_n * 32 + nt * 8 + (lane & 3) * 2;
            #pragma unroll
            for (int half = 0; half < 2; half++) {
                size_t row = bm + warp_m * 64 + mt * 16 + (lane >> 2) + half * 8;
                #pragma unroll
                for (int jc = 0; jc < 2; jc++) {
                    float v = acc[mt][nt][half * 2 + jc];
                    size_t cix = col + jc;
                    if (bias) v += bias[cix];
                    if (res)  v += res[row * (size_t)N + cix];
                    if (RELU) v = fmaxf(v, 0.f);
                    size_t o = row * (size_t)N + cix;
                    if (SPLIT) {
                        __nv_bfloat16 hh = __float2bfloat16(v);
                        Oh[o] = hh;
                        Ol[o] = __float2bfloat16(v - __bfloat162float(hh));
                    } else {
                        C[o] = v;
                    }
                }
            }
        }
    }
}

/* ================= weight transpose+split ================================ */
__global__ void wt_gen(const float* __restrict__ in, long in_zs,
                       __nv_bfloat16* __restrict__ oh, __nv_bfloat16* __restrict__ ol,
                       long out_zs, int Kd, int Nd) {
    __shared__ float t[32][33];
    int z = blockIdx.z;
    in += (size_t)z * in_zs; oh += (size_t)z * out_zs; ol += (size_t)z * out_zs;
    int n0 = blockIdx.x * 32, k0 = blockIdx.y * 32;
    int tx = threadIdx.x, ty = threadIdx.y;
    #pragma unroll
    for (int j = ty; j < 32; j += 8)
        t[j][tx] = in[(size_t)(k0 + j) * Nd + n0 + tx];
    __syncthreads();
    #pragma unroll
    for (int j = ty; j < 32; j += 8) {
        float v = t[tx][j];
        size_t o = (size_t)(n0 + j) * Kd + k0 + tx;
        __nv_bfloat16 h = __float2bfloat16(v);
        oh[o] = h;
        ol[o] = __float2bfloat16(v - __bfloat162float(h));
    }
}
__global__ void wt_qkv(const float* __restrict__ w,
                       __nv_bfloat16* __restrict__ oh, __nv_bfloat16* __restrict__ ol, int sel) {
    __shared__ float t[32][33];
    int z = blockIdx.z;            /* l*16 + h */
    int l = z >> 4, h = z & 15;
    const float* in = w + (size_t)z * E_DIM * HD;   /* [E][64] */
    size_t orow0 = (size_t)l * 3 * E_DIM + (size_t)sel * E_DIM + h * HD;
    __nv_bfloat16* ohp = oh + orow0 * E_DIM;
    __nv_bfloat16* olp = ol + orow0 * E_DIM;
    int d0 = blockIdx.x * 32, e0 = blockIdx.y * 32;
    int tx = threadIdx.x, ty = threadIdx.y;
    #pragma unroll
    for (int j = ty; j < 32; j += 8)
        t[j][tx] = in[(size_t)(e0 + j) * HD + d0 + tx];
    __syncthreads();
    #pragma unroll
    for (int j = ty; j < 32; j += 8) {
        float v = t[tx][j];
        size_t o = (size_t)(d0 + j) * E_DIM + e0 + tx;
        __nv_bfloat16 hh = __float2bfloat16(v);
        ohp[o] = hh;
        olp[o] = __float2bfloat16(v - __bfloat162float(hh));
    }
}

/* ================= elementwise kernels =================================== */
__global__ void embed_kernel(const int* __restrict__ idx, const float* __restrict__ emb,
                             float* __restrict__ x) {
    int i = blockIdx.x * blockDim.x + threadIdx.x;
    if (i < MTOK * E_DIM) {
        int m = i >> 10, e = i & 1023;
        x[i] = emb[(size_t)idx[m] * E_DIM + e];
    }
}

__global__ __launch_bounds__(256)
void ln_split_kernel(const float* __restrict__ x, const float* __restrict__ g,
                     const float* __restrict__ b,
                     __nv_bfloat16* __restrict__ yh, __nv_bfloat16* __restrict__ yl) {
    int m = blockIdx.x, tid = threadIdx.x;
    __shared__ float r1[256], r2[256];
    const float4* xr = (const float4*)(x + (size_t)m * E_DIM);
    float4 v = xr[tid];
    r1[tid] = v.x + v.y + v.z + v.w;
    r2[tid] = v.x * v.x + v.y * v.y + v.z * v.z + v.w * v.w;
    __syncthreads();
    for (int s = 128; s > 0; s >>= 1) {
        if (tid < s) { r1[tid] += r1[tid + s]; r2[tid] += r2[tid + s]; }
        __syncthreads();
    }
    float mean = r1[0] * (1.0f / E_DIM);
    float var  = r2[0] * (1.0f / E_DIM) - mean * mean;
    float rstd = rsqrtf(var + 1e-5f);
    float4 gg = ((const float4*)g)[tid];
    float4 bb = ((const float4*)b)[tid];
    float o[4] = { (v.x - mean) * rstd * gg.x + bb.x, (v.y - mean) * rstd * gg.y + bb.y,
                   (v.z - mean) * rstd * gg.z + bb.z, (v.w - mean) * rstd * gg.w + bb.w };
    size_t base = (size_t)m * E_DIM + tid * 4;
    #pragma unroll
    for (int j = 0; j < 4; j++) {
        __nv_bfloat16 h = __float2bfloat16(o[j]);
        yh[base + j] = h;
        yl[base + j] = __float2bfloat16(o[j] - __bfloat162float(h));
    }
}

__global__ void split_kernel(const float* __restrict__ x,
                             __nv_bfloat16* __restrict__ oh, __nv_bfloat16* __restrict__ ol, int n) {
    int i = blockIdx.x * blockDim.x + threadIdx.x;
    if (i < n) {
        float v = x[i];
        __nv_bfloat16 h = __float2bfloat16(v);
        oh[i] = h;
        ol[i] = __float2bfloat16(v - __bfloat162float(h));
    }
}

/* RoPE on qkv [M][3072]: rotate q (cols 0..1023) and k (1024..2047) */
__global__ void rope_kernel(float* __restrict__ qkv) {
    int i = blockIdx.x * blockDim.x + threadIdx.x;     /* MTOK * 1024 */
    if (i >= MTOK * 1024) return;
    int m = i >> 10;
    int r = i & 1023;
    int sec = r >> 9;          /* 0 = q, 1 = k */
    int h = (r >> 5) & 15;
    int p = r & 31;
    int t = m & (T_LEN - 1);
    float invf = powf(10000.f, -(float)(2 * p) / (float)HD);
    float sn, cs;
    sincosf((float)t * invf, &sn, &cs);
    float* base = qkv + (size_t)m * 3072 + sec * 1024 + h * 64 + 2 * p;
    float x0 = base[0], x1 = base[1];
    base[0] = x0 * cs - x1 * sn;
    base[1] = x0 * sn + x1 * cs;
}

/* fused causal attention; qkv [M][3072]; out split bf16 [M][E] */
__global__ __launch_bounds__(256)
void attn_kernel(const float* __restrict__ qkv,
                 __nv_bfloat16* __restrict__ oh, __nv_bfloat16* __restrict__ ol) {
    int t = blockIdx.x;
    int b = blockIdx.y >> 4;
    int h = blockIdx.y & 15;
    int m = b * T_LEN + t;
    const float* qr = qkv + (size_t)m * 3072 + h * 64;
    const float* kb = qkv + (size_t)b * T_LEN * 3072 + 1024 + h * 64;
    const float* vb = kb + 1024;

    __shared__ __align__(16) float qs[HD];
    __shared__ float sc[T_LEN];
    __shared__ float red[256];
    int tid = threadIdx.x;

    if (tid < 16) ((float4*)qs)[tid] = ((const float4*)qr)[tid];
    __syncthreads();

    const float scale = 0.03125f;
    for (int s = tid; s <= t; s += 256) {
        const float4* kr = (const float4*)(kb + (size_t)s * 3072);
        float acc = 0.f;
        #pragma unroll
        for (int i = 0; i < 16; i++) {
            float4 kv = kr[i];
            float4 qv = ((float4*)qs)[i];
            acc += kv.x * qv.x + kv.y * qv.y + kv.z * qv.z + kv.w * qv.w;
        }
        sc[s] = acc * scale;
    }
    __syncthreads();

    float mval = -1e30f;
    for (int s = tid; s <= t; s += 256) mval = fmaxf(mval, sc[s]);
    red[tid] = mval;
    __syncthreads();
    for (int s = 128; s > 0; s >>= 1) {
        if (tid < s) red[tid] = fmaxf(red[tid], red[tid + s]);
        __syncthreads();
    }
    float mx = red[0];
    __syncthreads();

    float sum = 0.f;
    for (int s = tid; s <= t; s += 256) {
        float e = __expf(sc[s] - mx);
        sc[s] = e;
        sum += e;
    }
    red[tid] = sum;
    __syncthreads();
    for (int s = 128; s > 0; s >>= 1) {
        if (tid < s) red[tid] += red[tid + s];
        __syncthreads();
    }
    float inv = 1.f / red[0];
    __syncthreads();

    int d  = tid & 63;
    int sg = tid >> 6;
    float acc = 0.f;
    for (int s = sg; s <= t; s += 4)
        acc += sc[s] * vb[(size_t)s * 3072 + d];
    red[tid] = acc;
    __syncthreads();
    if (sg == 0) {
        float v = (red[d] + red[64 + d] + red[128 + d] + red[192 + d]) * inv;
        size_t o = (size_t)m * E_DIM + h * 64 + d;
        __nv_bfloat16 hh = __float2bfloat16(v);
        oh[o] = hh;
        ol[o] = __float2bfloat16(v - __bfloat162float(hh));
    }
}

/* ================= NLL + loss ============================================ */
__global__ __launch_bounds__(256)
void nll_kernel(const float* __restrict__ logits, const int* __restrict__ tgt,
                float* __restrict__ nll) {
    int m = blockIdx.x, tid = threadIdx.x;
    const float* lr = logits + (size_t)m * VOCAB;
    __shared__ float red[256];
    float mx = -1e30f;
    for (int n = tid; n < VOCAB; n += 256) mx = fmaxf(mx, lr[n]);
    red[tid] = mx;
    __syncthreads();
    for (int s = 128; s > 0; s >>= 1) {
        if (tid < s) red[tid] = fmaxf(red[tid], red[tid + s]);
        __syncthreads();
    }
    mx = red[0];
    __syncthreads();
    float sum = 0.f;
    for (int n = tid; n < VOCAB; n += 256) sum += __expf(lr[n] - mx);
    red[tid] = sum;
    __syncthreads();
    for (int s = 128; s > 0; s >>= 1) {
        if (tid < s) red[tid] += red[tid + s];
        __syncthreads();
    }
    if (tid == 0)
        nll[m] = (logf(red[0]) + mx) - lr[tgt[m]];
}

__global__ __launch_bounds__(256)
void loss_reduce_kernel(const float* __restrict__ nll, float* __restrict__ out) {
    __shared__ float red[256];
    int tid = threadIdx.x;
    float s = 0.f;
    for (int i = tid; i < MTOK; i += 256) s += nll[i];
    red[tid] = s;
    __syncthreads();
    for (int k = 128; k > 0; k >>= 1) {
        if (tid < k) red[tid] += red[tid + k];
        __syncthreads();
    }
    if (tid == 0) out[0] = red[0] * (1.0f / MTOK);
}

/* ================= host orchestration ==================================== */
extern "C" void kernel_launch(void* const* d_in, const int* in_sizes, int n_in,
                              void* d_out, int out_size) {
    const int*   idx   = (const int*)  d_in[0];
    const int*   tgt   = (const int*)  d_in[1];
    const float* emb   = (const float*)d_in[2];
    const float* wq    = (const float*)d_in[3];
    const float* wk    = (const float*)d_in[4];
    const float* wv    = (const float*)d_in[5];
    const float* wproj = (const float*)d_in[6];
    const float* bproj = (const float*)d_in[7];
    const float* w1    = (const float*)d_in[8];
    const float* b1    = (const float*)d_in[9];
    const float* w2    = (const float*)d_in[10];
    const float* b2    = (const float*)d_in[11];
    const float* ln1g  = (const float*)d_in[12];
    const float* ln1b  = (const float*)d_in[13];
    const float* ln2g  = (const float*)d_in[14];
    const float* ln2b  = (const float*)d_in[15];
    const float* lm_w  = (const float*)d_in[16];
    const float* lm_b  = (const float*)d_in[17];

    float *x, *qkv, *nll, *lscr;
    __nv_bfloat16 *yh, *yl, *oh, *ol, *hh, *hl;
    __nv_bfloat16 *qkvTh, *qkvTl, *projTh, *projTl, *w1Th, *w1Tl, *w2Th, *w2Tl, *lmTh, *lmTl;
    cudaGetSymbolAddress((void**)&x,     g_x);
    cudaGetSymbolAddress((void**)&yh,    g_yh);
    cudaGetSymbolAddress((void**)&yl,    g_yl);
    cudaGetSymbolAddress((void**)&qkv,   g_qkv);
    cudaGetSymbolAddress((void**)&oh,    g_oh);
    cudaGetSymbolAddress((void**)&ol,    g_ol);
    cudaGetSymbolAddress((void**)&hh,    g_hh);
    cudaGetSymbolAddress((void**)&hl,    g_hl);
    cudaGetSymbolAddress((void**)&nll,   g_nllv);
    cudaGetSymbolAddress((void**)&lscr,  g_logits_scratch);
    cudaGetSymbolAddress((void**)&qkvTh, g_qkvT_h);
    cudaGetSymbolAddress((void**)&qkvTl, g_qkvT_l);
    cudaGetSymbolAddress((void**)&projTh, g_projT_h);
    cudaGetSymbolAddress((void**)&projTl, g_projT_l);
    cudaGetSymbolAddress((void**)&w1Th,  g_w1T_h);
    cudaGetSymbolAddress((void**)&w1Tl,  g_w1T_l);
    cudaGetSymbolAddress((void**)&w2Th,  g_w2T_h);
    cudaGetSymbolAddress((void**)&w2Tl,  g_w2T_l);
    cudaGetSymbolAddress((void**)&lmTh,  g_lmT_h);
    cudaGetSymbolAddress((void**)&lmTl,  g_lmT_l);

    cudaFuncSetAttribute(mma_gemm<false, false>, cudaFuncAttributeMaxDynamicSharedMemorySize, SMTOT);
    cudaFuncSetAttribute(mma_gemm<true,  true >, cudaFuncAttributeMaxDynamicSharedMemorySize, SMTOT);

    const long BTV = (long)MTOK * VOCAB;
    float* logits = ((long)out_size >= BTV) ? (float*)d_out : lscr;

    /* weight transpose + split (stateless each replay) */
    {
        dim3 tb(32, 8);
        wt_qkv<<<dim3(2, 32, N_LAYER * N_HEAD), tb>>>(wq, qkvTh, qkvTl, 0);
        wt_qkv<<<dim3(2, 32, N_LAYER * N_HEAD), tb>>>(wk, qkvTh, qkvTl, 1);
        wt_qkv<<<dim3(2, 32, N_LAYER * N_HEAD), tb>>>(wv, qkvTh, qkvTl, 2);
        wt_gen<<<dim3(32, 32, N_LAYER), tb>>>(wproj, (long)E_DIM * E_DIM, projTh, projTl,
                                              (long)E_DIM * E_DIM, E_DIM, E_DIM);
        wt_gen<<<dim3(128, 32, N_LAYER), tb>>>(w1, (long)E_DIM * FF, w1Th, w1Tl,
                                               (long)E_DIM * FF, E_DIM, FF);
        wt_gen<<<dim3(32, 128, N_LAYER), tb>>>(w2, (long)FF * E_DIM, w2Th, w2Tl,
                                               (long)FF * E_DIM, FF, E_DIM);
        wt_gen<<<dim3(1000, 32, 1), tb>>>(lm_w, 0, lmTh, lmTl, 0, E_DIM, VOCAB);
    }

    embed_kernel<<<(MTOK * E_DIM + 255) / 256, 256>>>(idx, emb, x);

    for (int l = 0; l < N_LAYER; l++) {
        size_t qkvW = (size_t)l * 3 * E_DIM * E_DIM;
        size_t prW  = (size_t)l * E_DIM * E_DIM;
        size_t w1W  = (size_t)l * FF * E_DIM;

        ln_split_kernel<<<MTOK, 256>>>(x, ln1g + (size_t)l * E_DIM, ln1b + (size_t)l * E_DIM, yh, yl);

        mma_gemm<false, false><<<dim3(3 * E_DIM / 128, MTOK / 128), 256, SMTOT>>>(
            yh, yl, qkvTh + qkvW, qkvTl + qkvW, E_DIM, 3 * E_DIM,
            qkv, nullptr, nullptr, nullptr, nullptr);

        rope_kernel<<<(MTOK * 1024 + 255) / 256, 256>>>(qkv);

        attn_kernel<<<dim3(T_LEN, BATCH * N_HEAD), 256>>>(qkv, oh, ol);

        mma_gemm<false, false><<<dim3(E_DIM / 128, MTOK / 128), 256, SMTOT>>>(
            oh, ol, projTh + prW, projTl + prW, E_DIM, E_DIM,
            x, nullptr, nullptr, bproj + (size_t)l * E_DIM, x);

        ln_split_kernel<<<MTOK, 256>>>(x, ln2g + (size_t)l * E_DIM, ln2b + (size_t)l * E_DIM, yh, yl);

        mma_gemm<true, true><<<dim3(FF / 128, MTOK / 128), 256, SMTOT>>>(
            yh, yl, w1Th + w1W, w1Tl + w1W, E_DIM, FF,
            nullptr, hh, hl, b1 + (size_t)l * FF, nullptr);

        mma_gemm<false, false><<<dim3(E_DIM / 128, MTOK / 128), 256, SMTOT>>>(
            hh, hl, w2Th + w1W, w2Tl + w1W, FF, E_DIM,
            x, nullptr, nullptr, b2 + (size_t)l * E_DIM, x);
    }

    split_kernel<<<(MTOK * E_DIM + 255) / 256, 256>>>(x, yh, yl, MTOK * E_DIM);

    mma_gemm<false, false><<<dim3(VOCAB / 128, MTOK / 128), 256, SMTOT>>>(
        yh, yl, lmTh, lmTl, E_DIM, VOCAB,
        logits, nullptr, nullptr, lm_b, nullptr);

    nll_kernel<<<MTOK, 256>>>(logits, tgt, nll);

    if ((long)out_size == BTV + 1) {
        loss_reduce_kernel<<<1, 256>>>(nll, (float*)d_out + BTV);
    } else if ((long)out_size < BTV) {
        loss_reduce_kernel<<<1, 256>>>(nll, (float*)d_out);
    }
}

// round 4
// speedup vs baseline: 1.6793x; 1.0583x over previous
#include <cuda_runtime.h>
#include <cuda_bf16.h>
#include <math.h>
#include <cstdint>

#define E_DIM   1024
#define N_HEAD  16
#define HD      64
#define T_LEN   1024
#define N_LAYER 6
#define VOCAB   32000
#define BATCH   2
#define MTOK    (BATCH * T_LEN)     /* 2048 */
#define FF      (4 * E_DIM)         /* 4096 */

/* ================= scratch =============================================== */
__device__ float g_x   [MTOK * E_DIM];
__device__ __nv_bfloat16 g_yh[MTOK * E_DIM];
__device__ __nv_bfloat16 g_yl[MTOK * E_DIM];
__device__ float g_qkv [MTOK * 3 * E_DIM];
__device__ __nv_bfloat16 g_oh[MTOK * E_DIM];
__device__ __nv_bfloat16 g_ol[MTOK * E_DIM];
__device__ __nv_bfloat16 g_hh[(size_t)MTOK * FF];
__device__ __nv_bfloat16 g_hl[(size_t)MTOK * FF];
__device__ float g_nllv[MTOK];
__device__ float g_logits_scratch[(size_t)MTOK * VOCAB];
/* transposed/split weights [N][K] bf16 */
__device__ __nv_bfloat16 g_qkvT_h[(size_t)N_LAYER * 3 * E_DIM * E_DIM];
__device__ __nv_bfloat16 g_qkvT_l[(size_t)N_LAYER * 3 * E_DIM * E_DIM];
__device__ __nv_bfloat16 g_projT_h[(size_t)N_LAYER * E_DIM * E_DIM];
__device__ __nv_bfloat16 g_projT_l[(size_t)N_LAYER * E_DIM * E_DIM];
__device__ __nv_bfloat16 g_w1T_h[(size_t)N_LAYER * FF * E_DIM];
__device__ __nv_bfloat16 g_w1T_l[(size_t)N_LAYER * FF * E_DIM];
__device__ __nv_bfloat16 g_w2T_h[(size_t)N_LAYER * E_DIM * FF];
__device__ __nv_bfloat16 g_w2T_l[(size_t)N_LAYER * E_DIM * FF];
__device__ __nv_bfloat16 g_lmT_h[(size_t)VOCAB * E_DIM];
__device__ __nv_bfloat16 g_lmT_l[(size_t)VOCAB * E_DIM];

/* ================= small PTX wrappers (base ISA only) ==================== */
__device__ __forceinline__ uint32_t smem_u32(const void* p) {
    uint32_t a;
    asm("{ .reg .u64 t; cvta.to.shared.u64 t, %1; cvt.u32.u64 %0, t; }" : "=r"(a) : "l"(p));
    return a;
}
__device__ __forceinline__ void cp16(uint32_t s, const void* g) {
    asm volatile("cp.async.cg.shared.global [%0], [%1], 16;" :: "r"(s), "l"(g));
}
__device__ __forceinline__ void cp_commit() { asm volatile("cp.async.commit_group;"); }
template<int N> __device__ __forceinline__ void cp_wait() {
    asm volatile("cp.async.wait_group %0;" :: "n"(N));
}
__device__ __forceinline__ void ldmA(uint32_t* r, uint32_t a) {
    asm volatile("ldmatrix.sync.aligned.m8n8.x4.shared.b16 {%0,%1,%2,%3}, [%4];"
                 : "=r"(r[0]), "=r"(r[1]), "=r"(r[2]), "=r"(r[3]) : "r"(a));
}
__device__ __forceinline__ void ldmB(uint32_t* r, uint32_t a) {
    asm volatile("ldmatrix.sync.aligned.m8n8.x2.shared.b16 {%0,%1}, [%2];"
                 : "=r"(r[0]), "=r"(r[1]) : "r"(a));
}
__device__ __forceinline__ void mma16816(float* c, const uint32_t* a, const uint32_t* b) {
    asm volatile("mma.sync.aligned.m16n8k16.row.col.f32.bf16.bf16.f32 "
                 "{%0,%1,%2,%3}, {%4,%5,%6,%7}, {%8,%9}, {%0,%1,%2,%3};"
                 : "+f"(c[0]), "+f"(c[1]), "+f"(c[2]), "+f"(c[3])
                 : "r"(a[0]), "r"(a[1]), "r"(a[2]), "r"(a[3]), "r"(b[0]), "r"(b[1]));
}

/* ================= HMMA GEMM ============================================= */
/* C[M,N] = (Ah+Al)[M,K] * (Bh+Bl)[N,K]^T   (3-MMA split-bf16, fp32 acc)     */
/* Block: 128x128, BK=32, 256 threads, 8 warps (2m x 4n), warp tile 64x32    */
/* 2 CTAs/SM (reg-capped), double-buffered cp.async, 1 sync per K chunk      */
#define ROWB   80                       /* padded smem row bytes */
#define TILEB  (128 * ROWB)             /* 10240 per operand tile */
#define STAGEB (4 * TILEB)              /* Ah Al Bh Bl = 40960 */
#define SMTOT  (2 * STAGEB)             /* 81920 */

template<bool RELU, bool SPLIT>
__global__ __launch_bounds__(256, 2)
void mma_gemm(const __nv_bfloat16* __restrict__ Ah, const __nv_bfloat16* __restrict__ Al,
              const __nv_bfloat16* __restrict__ Bh, const __nv_bfloat16* __restrict__ Bl,
              int K, int N,
              float* __restrict__ C,
              __nv_bfloat16* __restrict__ Oh, __nv_bfloat16* __restrict__ Ol,
              const float* __restrict__ bias, const float* __restrict__ res) {
    extern __shared__ char smem[];
    const uint32_t sb = smem_u32(smem);
    const int tid = threadIdx.x;
    const int lane = tid & 31;
    const int wid = tid >> 5;
    const int warp_m = wid & 1;
    const int warp_n = wid >> 1;
    const size_t bm = (size_t)blockIdx.y * 128;
    const size_t bn = (size_t)blockIdx.x * 128;

    float acc[4][4][4];
    #pragma unroll
    for (int i = 0; i < 4; i++)
        #pragma unroll
        for (int j = 0; j < 4; j++)
            #pragma unroll
            for (int q = 0; q < 4; q++) acc[i][j][q] = 0.f;

    const int nc = K >> 5;

    auto load_stage = [&](int c) {
        const int k0 = c << 5;
        const uint32_t sbase = sb + (c & 1) * STAGEB;
        #pragma unroll
        for (int t = 0; t < 8; t++) {
            int idx = tid + (t << 8);
            int tile = idx >> 9;                 /* 0 Ah, 1 Al, 2 Bh, 3 Bl */
            int r    = (idx >> 2) & 127;
            int cch  = idx & 3;
            const __nv_bfloat16* base = (tile == 0) ? Ah : (tile == 1) ? Al
                                      : (tile == 2) ? Bh : Bl;
            size_t grow = ((tile < 2) ? bm : bn) + r;
            const __nv_bfloat16* g = base + grow * (size_t)K + k0 + cch * 8;
            cp16(sbase + tile * TILEB + r * ROWB + cch * 16, g);
        }
        cp_commit();
    };

    load_stage(0);

    const uint32_t aRowOff = (uint32_t)((warp_m * 64 + (lane & 15)) * ROWB + ((lane >> 4) << 4));
    const uint32_t bRowOff = (uint32_t)((warp_n * 32 + (lane & 7)) * ROWB + (((lane >> 3) & 1) << 4));

    for (int c = 0; c < nc; c++) {
        cp_wait<0>();
        __syncthreads();
        if (c + 1 < nc) load_stage(c + 1);   /* overlaps compute below */

        const uint32_t st = sb + (c & 1) * STAGEB;
        const uint32_t aH = st + aRowOff;
        const uint32_t aL = st + TILEB + aRowOff;
        const uint32_t bH = st + 2 * TILEB + bRowOff;
        const uint32_t bL = st + 3 * TILEB + bRowOff;

        #pragma unroll
        for (int kk = 0; kk < 2; kk++) {
            const uint32_t kb = kk * 32;
            uint32_t a[4][4], bh[4][2], bl[4][2];
            #pragma unroll
            for (int nt = 0; nt < 4; nt++) {
                ldmB(bh[nt], bH + nt * (8 * ROWB) + kb);
                ldmB(bl[nt], bL + nt * (8 * ROWB) + kb);
            }
            #pragma unroll
            for (int mt = 0; mt < 4; mt++)
                ldmA(a[mt], aH + mt * (16 * ROWB) + kb);
            #pragma unroll
            for (int mt = 0; mt < 4; mt++)
                #pragma unroll
                for (int nt = 0; nt < 4; nt++)
                    mma16816(acc[mt][nt], a[mt], bh[nt]);
            #pragma unroll
            for (int mt = 0; mt < 4; mt++)
                #pragma unroll
                for (int nt = 0; nt < 4; nt++)
                    mma16816(acc[mt][nt], a[mt], bl[nt]);
            #pragma unroll
            for (int mt = 0; mt < 4; mt++)
                ldmA(a[mt], aL + mt * (16 * ROWB) + kb);   /* reuse regs */
            #pragma unroll
            for (int mt = 0; mt < 4; mt++)
                #pragma unroll
                for (int nt = 0; nt < 4; nt++)
                    mma16816(acc[mt][nt], a[mt], bh[nt]);
        }
    }

    /* epilogue */
    #pragma unroll
    for (int mt = 0; mt < 4; mt++) {
        #pragma unroll
        for (int nt = 0; nt < 4; nt++) {
            size_t col = bn + warp_n * 32 + nt * 8 + (lane & 3) * 2;
            #pragma unroll
            for (int half = 0; half < 2; half++) {
                size_t row = bm + warp_m * 64 + mt * 16 + (lane >> 2) + half * 8;
                #pragma unroll
                for (int jc = 0; jc < 2; jc++) {
                    float v = acc[mt][nt][half * 2 + jc];
                    size_t cix = col + jc;
                    if (bias) v += bias[cix];
                    if (res)  v += res[row * (size_t)N + cix];
                    if (RELU) v = fmaxf(v, 0.f);
                    size_t o = row * (size_t)N + cix;
                    if (SPLIT) {
                        __nv_bfloat16 hh = __float2bfloat16(v);
                        Oh[o] = hh;
                        Ol[o] = __float2bfloat16(v - __bfloat162float(hh));
                    } else {
                        C[o] = v;
                    }
                }
            }
        }
    }
}

/* ================= weight transpose+split ================================ */
__global__ void wt_gen(const float* __restrict__ in, long in_zs,
                       __nv_bfloat16* __restrict__ oh, __nv_bfloat16* __restrict__ ol,
                       long out_zs, int Kd, int Nd) {
    __shared__ float t[32][33];
    int z = blockIdx.z;
    in += (size_t)z * in_zs; oh += (size_t)z * out_zs; ol += (size_t)z * out_zs;
    int n0 = blockIdx.x * 32, k0 = blockIdx.y * 32;
    int tx = threadIdx.x, ty = threadIdx.y;
    #pragma unroll
    for (int j = ty; j < 32; j += 8)
        t[j][tx] = in[(size_t)(k0 + j) * Nd + n0 + tx];
    __syncthreads();
    #pragma unroll
    for (int j = ty; j < 32; j += 8) {
        float v = t[tx][j];
        size_t o = (size_t)(n0 + j) * Kd + k0 + tx;
        __nv_bfloat16 h = __float2bfloat16(v);
        oh[o] = h;
        ol[o] = __float2bfloat16(v - __bfloat162float(h));
    }
}
__global__ void wt_qkv(const float* __restrict__ w,
                       __nv_bfloat16* __restrict__ oh, __nv_bfloat16* __restrict__ ol, int sel) {
    __shared__ float t[32][33];
    int z = blockIdx.z;            /* l*16 + h */
    int l = z >> 4, h = z & 15;
    const float* in = w + (size_t)z * E_DIM * HD;   /* [E][64] */
    size_t orow0 = (size_t)l * 3 * E_DIM + (size_t)sel * E_DIM + h * HD;
    __nv_bfloat16* ohp = oh + orow0 * E_DIM;
    __nv_bfloat16* olp = ol + orow0 * E_DIM;
    int d0 = blockIdx.x * 32, e0 = blockIdx.y * 32;
    int tx = threadIdx.x, ty = threadIdx.y;
    #pragma unroll
    for (int j = ty; j < 32; j += 8)
        t[j][tx] = in[(size_t)(e0 + j) * HD + d0 + tx];
    __syncthreads();
    #pragma unroll
    for (int j = ty; j < 32; j += 8) {
        float v = t[tx][j];
        size_t o = (size_t)(d0 + j) * E_DIM + e0 + tx;
        __nv_bfloat16 hh = __float2bfloat16(v);
        ohp[o] = hh;
        olp[o] = __float2bfloat16(v - __bfloat162float(hh));
    }
}

/* ================= elementwise kernels =================================== */
__global__ void embed_kernel(const int* __restrict__ idx, const float* __restrict__ emb,
                             float* __restrict__ x) {
    int i = blockIdx.x * blockDim.x + threadIdx.x;
    if (i < MTOK * E_DIM) {
        int m = i >> 10, e = i & 1023;
        x[i] = emb[(size_t)idx[m] * E_DIM + e];
    }
}

__global__ __launch_bounds__(256)
void ln_split_kernel(const float* __restrict__ x, const float* __restrict__ g,
                     const float* __restrict__ b,
                     __nv_bfloat16* __restrict__ yh, __nv_bfloat16* __restrict__ yl) {
    int m = blockIdx.x, tid = threadIdx.x;
    __shared__ float r1[256], r2[256];
    const float4* xr = (const float4*)(x + (size_t)m * E_DIM);
    float4 v = xr[tid];
    r1[tid] = v.x + v.y + v.z + v.w;
    r2[tid] = v.x * v.x + v.y * v.y + v.z * v.z + v.w * v.w;
    __syncthreads();
    for (int s = 128; s > 0; s >>= 1) {
        if (tid < s) { r1[tid] += r1[tid + s]; r2[tid] += r2[tid + s]; }
        __syncthreads();
    }
    float mean = r1[0] * (1.0f / E_DIM);
    float var  = r2[0] * (1.0f / E_DIM) - mean * mean;
    float rstd = rsqrtf(var + 1e-5f);
    float4 gg = ((const float4*)g)[tid];
    float4 bb = ((const float4*)b)[tid];
    float o[4] = { (v.x - mean) * rstd * gg.x + bb.x, (v.y - mean) * rstd * gg.y + bb.y,
                   (v.z - mean) * rstd * gg.z + bb.z, (v.w - mean) * rstd * gg.w + bb.w };
    size_t base = (size_t)m * E_DIM + tid * 4;
    #pragma unroll
    for (int j = 0; j < 4; j++) {
        __nv_bfloat16 h = __float2bfloat16(o[j]);
        yh[base + j] = h;
        yl[base + j] = __float2bfloat16(o[j] - __bfloat162float(h));
    }
}

__global__ void split_kernel(const float* __restrict__ x,
                             __nv_bfloat16* __restrict__ oh, __nv_bfloat16* __restrict__ ol, int n) {
    int i = blockIdx.x * blockDim.x + threadIdx.x;
    if (i < n) {
        float v = x[i];
        __nv_bfloat16 h = __float2bfloat16(v);
        oh[i] = h;
        ol[i] = __float2bfloat16(v - __bfloat162float(h));
    }
}

/* RoPE on qkv [M][3072]: rotate q (cols 0..1023) and k (1024..2047) */
__global__ void rope_kernel(float* __restrict__ qkv) {
    int i = blockIdx.x * blockDim.x + threadIdx.x;     /* MTOK * 1024 */
    if (i >= MTOK * 1024) return;
    int m = i >> 10;
    int r = i & 1023;
    int sec = r >> 9;
    int h = (r >> 5) & 15;
    int p = r & 31;
    int t = m & (T_LEN - 1);
    float invf = powf(10000.f, -(float)(2 * p) / (float)HD);
    float sn, cs;
    sincosf((float)t * invf, &sn, &cs);
    float* base = qkv + (size_t)m * 3072 + sec * 1024 + h * 64 + 2 * p;
    float x0 = base[0], x1 = base[1];
    base[0] = x0 * cs - x1 * sn;
    base[1] = x0 * sn + x1 * cs;
}

/* fused causal attention; qkv [M][3072]; out split bf16 [M][E] */
__global__ __launch_bounds__(256)
void attn_kernel(const float* __restrict__ qkv,
                 __nv_bfloat16* __restrict__ oh, __nv_bfloat16* __restrict__ ol) {
    int t = blockIdx.x;
    int b = blockIdx.y >> 4;
    int h = blockIdx.y & 15;
    int m = b * T_LEN + t;
    const float* qr = qkv + (size_t)m * 3072 + h * 64;
    const float* kb = qkv + (size_t)b * T_LEN * 3072 + 1024 + h * 64;
    const float* vb = kb + 1024;

    __shared__ __align__(16) float qs[HD];
    __shared__ float sc[T_LEN];
    __shared__ float red[256];
    int tid = threadIdx.x;

    if (tid < 16) ((float4*)qs)[tid] = ((const float4*)qr)[tid];
    __syncthreads();

    const float scale = 0.03125f;
    for (int s = tid; s <= t; s += 256) {
        const float4* kr = (const float4*)(kb + (size_t)s * 3072);
        float acc = 0.f;
        #pragma unroll
        for (int i = 0; i < 16; i++) {
            float4 kv = kr[i];
            float4 qv = ((float4*)qs)[i];
            acc += kv.x * qv.x + kv.y * qv.y + kv.z * qv.z + kv.w * qv.w;
        }
        sc[s] = acc * scale;
    }
    __syncthreads();

    float mval = -1e30f;
    for (int s = tid; s <= t; s += 256) mval = fmaxf(mval, sc[s]);
    red[tid] = mval;
    __syncthreads();
    for (int s = 128; s > 0; s >>= 1) {
        if (tid < s) red[tid] = fmaxf(red[tid], red[tid + s]);
        __syncthreads();
    }
    float mx = red[0];
    __syncthreads();

    float sum = 0.f;
    for (int s = tid; s <= t; s += 256) {
        float e = __expf(sc[s] - mx);
        sc[s] = e;
        sum += e;
    }
    red[tid] = sum;
    __syncthreads();
    for (int s = 128; s > 0; s >>= 1) {
        if (tid < s) red[tid] += red[tid + s];
        __syncthreads();
    }
    float inv = 1.f / red[0];
    __syncthreads();

    int d  = tid & 63;
    int sg = tid >> 6;
    float acc = 0.f;
    for (int s = sg; s <= t; s += 4)
        acc += sc[s] * vb[(size_t)s * 3072 + d];
    red[tid] = acc;
    __syncthreads();
    if (sg == 0) {
        float v = (red[d] + red[64 + d] + red[128 + d] + red[192 + d]) * inv;
        size_t o = (size_t)m * E_DIM + h * 64 + d;
        __nv_bfloat16 hh = __float2bfloat16(v);
        oh[o] = hh;
        ol[o] = __float2bfloat16(v - __bfloat162float(hh));
    }
}

/* ================= NLL + loss ============================================ */
__global__ __launch_bounds__(256)
void nll_kernel(const float* __restrict__ logits, const int* __restrict__ tgt,
                float* __restrict__ nll) {
    int m = blockIdx.x, tid = threadIdx.x;
    const float* lr = logits + (size_t)m * VOCAB;
    __shared__ float red[256];
    float mx = -1e30f;
    for (int n = tid; n < VOCAB; n += 256) mx = fmaxf(mx, lr[n]);
    red[tid] = mx;
    __syncthreads();
    for (int s = 128; s > 0; s >>= 1) {
        if (tid < s) red[tid] = fmaxf(red[tid], red[tid + s]);
        __syncthreads();
    }
    mx = red[0];
    __syncthreads();
    float sum = 0.f;
    for (int n = tid; n < VOCAB; n += 256) sum += __expf(lr[n] - mx);
    red[tid] = sum;
    __syncthreads();
    for (int s = 128; s > 0; s >>= 1) {
        if (tid < s) red[tid] += red[tid + s];
        __syncthreads();
    }
    if (tid == 0)
        nll[m] = (logf(red[0]) + mx) - lr[tgt[m]];
}

__global__ __launch_bounds__(256)
void loss_reduce_kernel(const float* __restrict__ nll, float* __restrict__ out) {
    __shared__ float red[256];
    int tid = threadIdx.x;
    float s = 0.f;
    for (int i = tid; i < MTOK; i += 256) s += nll[i];
    red[tid] = s;
    __syncthreads();
    for (int k = 128; k > 0; k >>= 1) {
        if (tid < k) red[tid] += red[tid + k];
        __syncthreads();
    }
    if (tid == 0) out[0] = red[0] * (1.0f / MTOK);
}

/* ================= host orchestration ==================================== */
extern "C" void kernel_launch(void* const* d_in, const int* in_sizes, int n_in,
                              void* d_out, int out_size) {
    const int*   idx   = (const int*)  d_in[0];
    const int*   tgt   = (const int*)  d_in[1];
    const float* emb   = (const float*)d_in[2];
    const float* wq    = (const float*)d_in[3];
    const float* wk    = (const float*)d_in[4];
    const float* wv    = (const float*)d_in[5];
    const float* wproj = (const float*)d_in[6];
    const float* bproj = (const float*)d_in[7];
    const float* w1    = (const float*)d_in[8];
    const float* b1    = (const float*)d_in[9];
    const float* w2    = (const float*)d_in[10];
    const float* b2    = (const float*)d_in[11];
    const float* ln1g  = (const float*)d_in[12];
    const float* ln1b  = (const float*)d_in[13];
    const float* ln2g  = (const float*)d_in[14];
    const float* ln2b  = (const float*)d_in[15];
    const float* lm_w  = (const float*)d_in[16];
    const float* lm_b  = (const float*)d_in[17];

    float *x, *qkv, *nll, *lscr;
    __nv_bfloat16 *yh, *yl, *oh, *ol, *hh, *hl;
    __nv_bfloat16 *qkvTh, *qkvTl, *projTh, *projTl, *w1Th, *w1Tl, *w2Th, *w2Tl, *lmTh, *lmTl;
    cudaGetSymbolAddress((void**)&x,     g_x);
    cudaGetSymbolAddress((void**)&yh,    g_yh);
    cudaGetSymbolAddress((void**)&yl,    g_yl);
    cudaGetSymbolAddress((void**)&qkv,   g_qkv);
    cudaGetSymbolAddress((void**)&oh,    g_oh);
    cudaGetSymbolAddress((void**)&ol,    g_ol);
    cudaGetSymbolAddress((void**)&hh,    g_hh);
    cudaGetSymbolAddress((void**)&hl,    g_hl);
    cudaGetSymbolAddress((void**)&nll,   g_nllv);
    cudaGetSymbolAddress((void**)&lscr,  g_logits_scratch);
    cudaGetSymbolAddress((void**)&qkvTh, g_qkvT_h);
    cudaGetSymbolAddress((void**)&qkvTl, g_qkvT_l);
    cudaGetSymbolAddress((void**)&projTh, g_projT_h);
    cudaGetSymbolAddress((void**)&projTl, g_projT_l);
    cudaGetSymbolAddress((void**)&w1Th,  g_w1T_h);
    cudaGetSymbolAddress((void**)&w1Tl,  g_w1T_l);
    cudaGetSymbolAddress((void**)&w2Th,  g_w2T_h);
    cudaGetSymbolAddress((void**)&w2Tl,  g_w2T_l);
    cudaGetSymbolAddress((void**)&lmTh,  g_lmT_h);
    cudaGetSymbolAddress((void**)&lmTl,  g_lmT_l);

    cudaFuncSetAttribute(mma_gemm<false, false>, cudaFuncAttributeMaxDynamicSharedMemorySize, SMTOT);
    cudaFuncSetAttribute(mma_gemm<true,  true >, cudaFuncAttributeMaxDynamicSharedMemorySize, SMTOT);

    const long BTV = (long)MTOK * VOCAB;
    float* logits = ((long)out_size >= BTV) ? (float*)d_out : lscr;

    dim3 tb(32, 8);
    /* launches 1-5, so launch 6 (ncu -s 5 -c 1 capture) is the QKV GEMM */
    embed_kernel<<<(MTOK * E_DIM + 255) / 256, 256>>>(idx, emb, x);                 /* 1 */
    wt_qkv<<<dim3(2, 32, N_LAYER * N_HEAD), tb>>>(wq, qkvTh, qkvTl, 0);             /* 2 */
    wt_qkv<<<dim3(2, 32, N_LAYER * N_HEAD), tb>>>(wk, qkvTh, qkvTl, 1);             /* 3 */
    wt_qkv<<<dim3(2, 32, N_LAYER * N_HEAD), tb>>>(wv, qkvTh, qkvTl, 2);             /* 4 */
    ln_split_kernel<<<MTOK, 256>>>(x, ln1g, ln1b, yh, yl);                          /* 5 */
    mma_gemm<false, false><<<dim3(3 * E_DIM / 128, MTOK / 128), 256, SMTOT>>>(      /* 6 */
        yh, yl, qkvTh, qkvTl, E_DIM, 3 * E_DIM,
        qkv, nullptr, nullptr, nullptr, nullptr);

    /* remaining weight transposes (before first use) */
    wt_gen<<<dim3(32, 32, N_LAYER), tb>>>(wproj, (long)E_DIM * E_DIM, projTh, projTl,
                                          (long)E_DIM * E_DIM, E_DIM, E_DIM);
    wt_gen<<<dim3(128, 32, N_LAYER), tb>>>(w1, (long)E_DIM * FF, w1Th, w1Tl,
                                           (long)E_DIM * FF, E_DIM, FF);
    wt_gen<<<dim3(32, 128, N_LAYER), tb>>>(w2, (long)FF * E_DIM, w2Th, w2Tl,
                                           (long)FF * E_DIM, FF, E_DIM);
    wt_gen<<<dim3(1000, 32, 1), tb>>>(lm_w, 0, lmTh, lmTl, 0, E_DIM, VOCAB);

    for (int l = 0; l < N_LAYER; l++) {
        size_t qkvW = (size_t)l * 3 * E_DIM * E_DIM;
        size_t prW  = (size_t)l * E_DIM * E_DIM;
        size_t w1W  = (size_t)l * FF * E_DIM;

        if (l > 0) {
            ln_split_kernel<<<MTOK, 256>>>(x, ln1g + (size_t)l * E_DIM, ln1b + (size_t)l * E_DIM, yh, yl);
            mma_gemm<false, false><<<dim3(3 * E_DIM / 128, MTOK / 128), 256, SMTOT>>>(
                yh, yl, qkvTh + qkvW, qkvTl + qkvW, E_DIM, 3 * E_DIM,
                qkv, nullptr, nullptr, nullptr, nullptr);
        }

        rope_kernel<<<(MTOK * 1024 + 255) / 256, 256>>>(qkv);

        attn_kernel<<<dim3(T_LEN, BATCH * N_HEAD), 256>>>(qkv, oh, ol);

        mma_gemm<false, false><<<dim3(E_DIM / 128, MTOK / 128), 256, SMTOT>>>(
            oh, ol, projTh + prW, projTl + prW, E_DIM, E_DIM,
            x, nullptr, nullptr, bproj + (size_t)l * E_DIM, x);

        ln_split_kernel<<<MTOK, 256>>>(x, ln2g + (size_t)l * E_DIM, ln2b + (size_t)l * E_DIM, yh, yl);

        mma_gemm<true, true><<<dim3(FF / 128, MTOK / 128), 256, SMTOT>>>(
            yh, yl, w1Th + w1W, w1Tl + w1W, E_DIM, FF,
            nullptr, hh, hl, b1 + (size_t)l * FF, nullptr);

        mma_gemm<false, false><<<dim3(E_DIM / 128, MTOK / 128), 256, SMTOT>>>(
            hh, hl, w2Th + w1W, w2Tl + w1W, FF, E_DIM,
            x, nullptr, nullptr, b2 + (size_t)l * E_DIM, x);
    }

    split_kernel<<<(MTOK * E_DIM + 255) / 256, 256>>>(x, yh, yl, MTOK * E_DIM);

    mma_gemm<false, false><<<dim3(VOCAB / 128, MTOK / 128), 256, SMTOT>>>(
        yh, yl, lmTh, lmTl, E_DIM, VOCAB,
        logits, nullptr, nullptr, lm_b, nullptr);

    nll_kernel<<<MTOK, 256>>>(logits, tgt, nll);

    if ((long)out_size == BTV + 1) {
        loss_reduce_kernel<<<1, 256>>>(nll, (float*)d_out + BTV);
    } else if ((long)out_size < BTV) {
        loss_reduce_kernel<<<1, 256>>>(nll, (float*)d_out);
    }
}

// round 6
// speedup vs baseline: 3.1175x; 1.8564x over previous
#include <cuda_runtime.h>
#include <cuda_bf16.h>
#include <math.h>
#include <cstdint>

#define E_DIM   1024
#define N_HEAD  16
#define HD      64
#define T_LEN   1024
#define N_LAYER 6
#define VOCAB   32000
#define BATCH   2
#define MTOK    (BATCH * T_LEN)     /* 2048 */
#define FF      (4 * E_DIM)         /* 4096 */
#define QG      8                   /* queries per attention block */

/* ================= scratch =============================================== */
__device__ float g_x   [MTOK * E_DIM];
__device__ __nv_bfloat16 g_yh[MTOK * E_DIM];
__device__ __nv_bfloat16 g_yl[MTOK * E_DIM];
__device__ float g_qkv [MTOK * 3 * E_DIM];
__device__ __nv_bfloat16 g_oh[MTOK * E_DIM];
__device__ __nv_bfloat16 g_ol[MTOK * E_DIM];
__device__ __nv_bfloat16 g_hh[(size_t)MTOK * FF];
__device__ __nv_bfloat16 g_hl[(size_t)MTOK * FF];
__device__ float g_nllv[MTOK];
__device__ float g_logits_scratch[(size_t)MTOK * VOCAB];
__device__ float2 g_cs[T_LEN * 32];          /* rope cos/sin table */
/* transposed/split weights [N][K] bf16 */
__device__ __nv_bfloat16 g_qkvT_h[(size_t)N_LAYER * 3 * E_DIM * E_DIM];
__device__ __nv_bfloat16 g_qkvT_l[(size_t)N_LAYER * 3 * E_DIM * E_DIM];
__device__ __nv_bfloat16 g_projT_h[(size_t)N_LAYER * E_DIM * E_DIM];
__device__ __nv_bfloat16 g_projT_l[(size_t)N_LAYER * E_DIM * E_DIM];
__device__ __nv_bfloat16 g_w1T_h[(size_t)N_LAYER * FF * E_DIM];
__device__ __nv_bfloat16 g_w1T_l[(size_t)N_LAYER * FF * E_DIM];
__device__ __nv_bfloat16 g_w2T_h[(size_t)N_LAYER * E_DIM * FF];
__device__ __nv_bfloat16 g_w2T_l[(size_t)N_LAYER * E_DIM * FF];
__device__ __nv_bfloat16 g_lmT_h[(size_t)VOCAB * E_DIM];
__device__ __nv_bfloat16 g_lmT_l[(size_t)VOCAB * E_DIM];

/* ================= small PTX wrappers (base ISA only) ==================== */
__device__ __forceinline__ uint32_t smem_u32(const void* p) {
    uint32_t a;
    asm("{ .reg .u64 t; cvta.to.shared.u64 t, %1; cvt.u32.u64 %0, t; }" : "=r"(a) : "l"(p));
    return a;
}
__device__ __forceinline__ void cp16(uint32_t s, const void* g) {
    asm volatile("cp.async.cg.shared.global [%0], [%1], 16;" :: "r"(s), "l"(g));
}
__device__ __forceinline__ void cp_commit() { asm volatile("cp.async.commit_group;"); }
template<int N> __device__ __forceinline__ void cp_wait() {
    asm volatile("cp.async.wait_group %0;" :: "n"(N));
}
__device__ __forceinline__ void ldmA(uint32_t* r, uint32_t a) {
    asm volatile("ldmatrix.sync.aligned.m8n8.x4.shared.b16 {%0,%1,%2,%3}, [%4];"
                 : "=r"(r[0]), "=r"(r[1]), "=r"(r[2]), "=r"(r[3]) : "r"(a));
}
__device__ __forceinline__ void ldmB(uint32_t* r, uint32_t a) {
    asm volatile("ldmatrix.sync.aligned.m8n8.x2.shared.b16 {%0,%1}, [%2];"
                 : "=r"(r[0]), "=r"(r[1]) : "r"(a));
}
__device__ __forceinline__ void mma16816(float* c, const uint32_t* a, const uint32_t* b) {
    asm volatile("mma.sync.aligned.m16n8k16.row.col.f32.bf16.bf16.f32 "
                 "{%0,%1,%2,%3}, {%4,%5,%6,%7}, {%8,%9}, {%0,%1,%2,%3};"
                 : "+f"(c[0]), "+f"(c[1]), "+f"(c[2]), "+f"(c[3])
                 : "r"(a[0]), "r"(a[1]), "r"(a[2]), "r"(a[3]), "r"(b[0]), "r"(b[1]));
}

/* ================= HMMA GEMM ============================================= */
#define ROWB   80
#define TILEB  (128 * ROWB)
#define STAGEB (4 * TILEB)
#define SMTOT  (2 * STAGEB)

template<bool RELU, bool SPLIT, bool ROPE>
__global__ __launch_bounds__(256, 2)
void mma_gemm(const __nv_bfloat16* __restrict__ Ah, const __nv_bfloat16* __restrict__ Al,
              const __nv_bfloat16* __restrict__ Bh, const __nv_bfloat16* __restrict__ Bl,
              int K, int N,
              float* __restrict__ C,
              __nv_bfloat16* __restrict__ Oh, __nv_bfloat16* __restrict__ Ol,
              const float* __restrict__ bias, const float* __restrict__ res,
              const float2* __restrict__ cs) {
    extern __shared__ char smem[];
    const uint32_t sb = smem_u32(smem);
    const int tid = threadIdx.x;
    const int lane = tid & 31;
    const int wid = tid >> 5;
    const int warp_m = wid & 1;
    const int warp_n = wid >> 1;
    const size_t bm = (size_t)blockIdx.y * 128;
    const size_t bn = (size_t)blockIdx.x * 128;

    float acc[4][4][4];
    #pragma unroll
    for (int i = 0; i < 4; i++)
        #pragma unroll
        for (int j = 0; j < 4; j++)
            #pragma unroll
            for (int q = 0; q < 4; q++) acc[i][j][q] = 0.f;

    const int nc = K >> 5;

    auto load_stage = [&](int c) {
        const int k0 = c << 5;
        const uint32_t sbase = sb + (c & 1) * STAGEB;
        #pragma unroll
        for (int t = 0; t < 8; t++) {
            int idx = tid + (t << 8);
            int tile = idx >> 9;
            int r    = (idx >> 2) & 127;
            int cch  = idx & 3;
            const __nv_bfloat16* base = (tile == 0) ? Ah : (tile == 1) ? Al
                                      : (tile == 2) ? Bh : Bl;
            size_t grow = ((tile < 2) ? bm : bn) + r;
            const __nv_bfloat16* g = base + grow * (size_t)K + k0 + cch * 8;
            cp16(sbase + tile * TILEB + r * ROWB + cch * 16, g);
        }
        cp_commit();
    };

    load_stage(0);

    const uint32_t aRowOff = (uint32_t)((warp_m * 64 + (lane & 15)) * ROWB + ((lane >> 4) << 4));
    const uint32_t bRowOff = (uint32_t)((warp_n * 32 + (lane & 7)) * ROWB + (((lane >> 3) & 1) << 4));

    for (int c = 0; c < nc; c++) {
        cp_wait<0>();
        __syncthreads();
        if (c + 1 < nc) load_stage(c + 1);

        const uint32_t st = sb + (c & 1) * STAGEB;
        const uint32_t aH = st + aRowOff;
        const uint32_t aL = st + TILEB + aRowOff;
        const uint32_t bH = st + 2 * TILEB + bRowOff;
        const uint32_t bL = st + 3 * TILEB + bRowOff;

        #pragma unroll
        for (int kk = 0; kk < 2; kk++) {
            const uint32_t kb = kk * 32;
            uint32_t a[4][4], bh[4][2], bl[4][2];
            #pragma unroll
            for (int nt = 0; nt < 4; nt++) {
                ldmB(bh[nt], bH + nt * (8 * ROWB) + kb);
                ldmB(bl[nt], bL + nt * (8 * ROWB) + kb);
            }
            #pragma unroll
            for (int mt = 0; mt < 4; mt++)
                ldmA(a[mt], aH + mt * (16 * ROWB) + kb);
            #pragma unroll
            for (int mt = 0; mt < 4; mt++)
                #pragma unroll
                for (int nt = 0; nt < 4; nt++)
                    mma16816(acc[mt][nt], a[mt], bh[nt]);
            #pragma unroll
            for (int mt = 0; mt < 4; mt++)
                #pragma unroll
                for (int nt = 0; nt < 4; nt++)
                    mma16816(acc[mt][nt], a[mt], bl[nt]);
            #pragma unroll
            for (int mt = 0; mt < 4; mt++)
                ldmA(a[mt], aL + mt * (16 * ROWB) + kb);
            #pragma unroll
            for (int mt = 0; mt < 4; mt++)
                #pragma unroll
                for (int nt = 0; nt < 4; nt++)
                    mma16816(acc[mt][nt], a[mt], bh[nt]);
        }
    }

    /* epilogue (pairwise; rope rotates (col,col+1) pairs in q/k sections) */
    #pragma unroll
    for (int mt = 0; mt < 4; mt++) {
        #pragma unroll
        for (int nt = 0; nt < 4; nt++) {
            size_t col = bn + warp_n * 32 + nt * 8 + (lane & 3) * 2;
            #pragma unroll
            for (int half = 0; half < 2; half++) {
                size_t row = bm + warp_m * 64 + mt * 16 + (lane >> 2) + half * 8;
                float v0 = acc[mt][nt][half * 2 + 0];
                float v1 = acc[mt][nt][half * 2 + 1];
                if (bias) { v0 += bias[col]; v1 += bias[col + 1]; }
                if (res) {
                    const float2 r2 = *(const float2*)(res + row * (size_t)N + col);
                    v0 += r2.x; v1 += r2.y;
                }
                if (RELU) { v0 = fmaxf(v0, 0.f); v1 = fmaxf(v1, 0.f); }
                if (ROPE && col < 2048) {
                    int t = (int)(row & (T_LEN - 1));
                    int p = ((int)col & 63) >> 1;
                    float2 c2 = cs[t * 32 + p];
                    float r0 = v0 * c2.x - v1 * c2.y;
                    float r1 = v0 * c2.y + v1 * c2.x;
                    v0 = r0; v1 = r1;
                }
                size_t o = row * (size_t)N + col;
                if (SPLIT) {
                    __nv_bfloat16 h0 = __float2bfloat16(v0);
                    __nv_bfloat16 h1 = __float2bfloat16(v1);
                    Oh[o] = h0;     Ol[o] = __float2bfloat16(v0 - __bfloat162float(h0));
                    Oh[o + 1] = h1; Ol[o + 1] = __float2bfloat16(v1 - __bfloat162float(h1));
                } else {
                    *(float2*)(C + o) = make_float2(v0, v1);
                }
            }
        }
    }
}

/* ================= weight transpose+split ================================ */
__global__ void wt_gen(const float* __restrict__ in, long in_zs,
                       __nv_bfloat16* __restrict__ oh, __nv_bfloat16* __restrict__ ol,
                       long out_zs, int Kd, int Nd) {
    __shared__ float t[32][33];
    int z = blockIdx.z;
    in += (size_t)z * in_zs; oh += (size_t)z * out_zs; ol += (size_t)z * out_zs;
    int n0 = blockIdx.x * 32, k0 = blockIdx.y * 32;
    int tx = threadIdx.x, ty = threadIdx.y;
    #pragma unroll
    for (int j = ty; j < 32; j += 8)
        t[j][tx] = in[(size_t)(k0 + j) * Nd + n0 + tx];
    __syncthreads();
    #pragma unroll
    for (int j = ty; j < 32; j += 8) {
        float v = t[tx][j];
        size_t o = (size_t)(n0 + j) * Kd + k0 + tx;
        __nv_bfloat16 h = __float2bfloat16(v);
        oh[o] = h;
        ol[o] = __float2bfloat16(v - __bfloat162float(h));
    }
}
/* combined q/k/v transpose: z encodes sel(0..2), layer, head */
__global__ void wt_qkv_all(const float* __restrict__ wq, const float* __restrict__ wk,
                           const float* __restrict__ wv,
                           __nv_bfloat16* __restrict__ oh, __nv_bfloat16* __restrict__ ol) {
    __shared__ float t[32][33];
    int z = blockIdx.z;                 /* 0..287 */
    int sel = z / 96;
    int zz  = z - sel * 96;             /* l*16 + h */
    int l = zz >> 4, h = zz & 15;
    const float* w = (sel == 0) ? wq : (sel == 1) ? wk : wv;
    const float* in = w + (size_t)zz * E_DIM * HD;
    size_t orow0 = (size_t)l * 3 * E_DIM + (size_t)sel * E_DIM + h * HD;
    __nv_bfloat16* ohp = oh + orow0 * E_DIM;
    __nv_bfloat16* olp = ol + orow0 * E_DIM;
    int d0 = blockIdx.x * 32, e0 = blockIdx.y * 32;
    int tx = threadIdx.x, ty = threadIdx.y;
    #pragma unroll
    for (int j = ty; j < 32; j += 8)
        t[j][tx] = in[(size_t)(e0 + j) * HD + d0 + tx];
    __syncthreads();
    #pragma unroll
    for (int j = ty; j < 32; j += 8) {
        float v = t[tx][j];
        size_t o = (size_t)(d0 + j) * E_DIM + e0 + tx;
        __nv_bfloat16 hh = __float2bfloat16(v);
        ohp[o] = hh;
        olp[o] = __float2bfloat16(v - __bfloat162float(hh));
    }
}

/* ================= elementwise kernels =================================== */
/* embed gather + rope cos/sin table fill */
__global__ void embed_kernel(const int* __restrict__ idx, const float* __restrict__ emb,
                             float* __restrict__ x) {
    int i = blockIdx.x * blockDim.x + threadIdx.x;
    if (i < MTOK * E_DIM) {
        int m = i >> 10, e = i & 1023;
        x[i] = emb[(size_t)idx[m] * E_DIM + e];
    }
    if (i < T_LEN * 32) {
        int t = i >> 5, p = i & 31;
        float invf = powf(10000.f, -(float)(2 * p) / (float)HD);
        float sn, c;
        sincosf((float)t * invf, &sn, &c);
        g_cs[i] = make_float2(c, sn);
    }
}

__global__ __launch_bounds__(256)
void ln_split_kernel(const float* __restrict__ x, const float* __restrict__ g,
                     const float* __restrict__ b,
                     __nv_bfloat16* __restrict__ yh, __nv_bfloat16* __restrict__ yl) {
    int m = blockIdx.x, tid = threadIdx.x;
    __shared__ float r1[256], r2[256];
    const float4* xr = (const float4*)(x + (size_t)m * E_DIM);
    float4 v = xr[tid];
    r1[tid] = v.x + v.y + v.z + v.w;
    r2[tid] = v.x * v.x + v.y * v.y + v.z * v.z + v.w * v.w;
    __syncthreads();
    for (int s = 128; s > 0; s >>= 1) {
        if (tid < s) { r1[tid] += r1[tid + s]; r2[tid] += r2[tid + s]; }
        __syncthreads();
    }
    float mean = r1[0] * (1.0f / E_DIM);
    float var  = r2[0] * (1.0f / E_DIM) - mean * mean;
    float rstd = rsqrtf(var + 1e-5f);
    float4 gg = ((const float4*)g)[tid];
    float4 bb = ((const float4*)b)[tid];
    float o[4] = { (v.x - mean) * rstd * gg.x + bb.x, (v.y - mean) * rstd * gg.y + bb.y,
                   (v.z - mean) * rstd * gg.z + bb.z, (v.w - mean) * rstd * gg.w + bb.w };
    size_t base = (size_t)m * E_DIM + tid * 4;
    #pragma unroll
    for (int j = 0; j < 4; j++) {
        __nv_bfloat16 h = __float2bfloat16(o[j]);
        yh[base + j] = h;
        yl[base + j] = __float2bfloat16(o[j] - __bfloat162float(h));
    }
}

__global__ void split_kernel(const float* __restrict__ x,
                             __nv_bfloat16* __restrict__ oh, __nv_bfloat16* __restrict__ ol, int n) {
    int i = blockIdx.x * blockDim.x + threadIdx.x;
    if (i < n) {
        float v = x[i];
        __nv_bfloat16 h = __float2bfloat16(v);
        oh[i] = h;
        ol[i] = __float2bfloat16(v - __bfloat162float(h));
    }
}

/* ======== tiled causal attention: block = (b,h, 8-query tile) ============ */
__global__ __launch_bounds__(256)
void attn_kernel(const float* __restrict__ qkv,
                 __nv_bfloat16* __restrict__ oh, __nv_bfloat16* __restrict__ ol) {
    const int qt = blockIdx.x;               /* 0..T_LEN/QG-1 */
    const int b  = blockIdx.y >> 4;
    const int h  = blockIdx.y & 15;
    const int t0 = qt * QG;
    const int tid = threadIdx.x, lane = tid & 31, w = tid >> 5;

    const float* qb = qkv + (size_t)b * T_LEN * 3072 + h * 64;
    const float* kb = qb + 1024;
    const float* vb = qb + 2048;

    __shared__ __align__(16) float qs[QG][64];
    __shared__ float sc[QG][T_LEN];
    __shared__ float sinv[QG];

    if (tid < QG * 16) {
        int q = tid >> 4, c = tid & 15;
        ((float4*)qs[q])[c] = ((const float4*)(qb + (size_t)(t0 + q) * 3072))[c];
    }
    __syncthreads();

    const float scale = 0.03125f;            /* n_embd^-0.5 */
    const int nk = t0 + QG;                  /* keys 0..t0+QG-1 cover all queries */
    for (int k = tid; k < nk; k += 256) {
        const float4* kr = (const float4*)(kb + (size_t)k * 3072);
        float a[QG] = {};
        #pragma unroll 4
        for (int c = 0; c < 16; c++) {
            float4 kv = kr[c];
            #pragma unroll
            for (int q = 0; q < QG; q++) {
                float4 qv = ((float4*)qs[q])[c];
                a[q] += kv.x * qv.x + kv.y * qv.y + kv.z * qv.z + kv.w * qv.w;
            }
        }
        #pragma unroll
        for (int q = 0; q < QG; q++) sc[q][k] = a[q] * scale;
    }
    __syncthreads();

    /* warp w handles query w: softmax over k in [0, t0+w] */
    {
        const int n = t0 + w + 1;
        float m = -1e30f;
        for (int k = lane; k < n; k += 32) m = fmaxf(m, sc[w][k]);
        #pragma unroll
        for (int o = 16; o > 0; o >>= 1) m = fmaxf(m, __shfl_xor_sync(~0u, m, o));
        float s = 0.f;
        for (int k = lane; k < n; k += 32) {
            float e = __expf(sc[w][k] - m);
            sc[w][k] = e;
            s += e;
        }
        #pragma unroll
        for (int o = 16; o > 0; o >>= 1) s += __shfl_xor_sync(~0u, s, o);
        if (lane == 0) sinv[w] = 1.f / s;
    }
    __syncthreads();

    /* PV: warp w = query w; lane covers dims (2*lane, 2*lane+1) */
    {
        const int n = t0 + w + 1;
        float acc0 = 0.f, acc1 = 0.f;
        const float* vp = vb + 2 * lane;
        int k = 0;
        for (; k + 1 < n; k += 2) {
            float p0 = sc[w][k], p1 = sc[w][k + 1];
            float2 v0 = *(const float2*)(vp + (size_t)k * 3072);
            float2 v1 = *(const float2*)(vp + (size_t)(k + 1) * 3072);
            acc0 += p0 * v0.x + p1 * v1.x;
            acc1 += p0 * v0.y + p1 * v1.y;
        }
        if (k < n) {
            float p = sc[w][k];
            float2 vv = *(const float2*)(vp + (size_t)k * 3072);
            acc0 += p * vv.x; acc1 += p * vv.y;
        }
        float inv = sinv[w];
        float o0 = acc0 * inv, o1 = acc1 * inv;
        size_t o = (size_t)(b * T_LEN + t0 + w) * E_DIM + h * 64 + 2 * lane;
        __nv_bfloat16 h0 = __float2bfloat16(o0);
        __nv_bfloat16 h1 = __float2bfloat16(o1);
        oh[o] = h0;     ol[o] = __float2bfloat16(o0 - __bfloat162float(h0));
        oh[o + 1] = h1; ol[o + 1] = __float2bfloat16(o1 - __bfloat162float(h1));
    }
}

/* ================= NLL + loss ============================================ */
__global__ __launch_bounds__(256)
void nll_kernel(const float* __restrict__ logits, const int* __restrict__ tgt,
                float* __restrict__ nll) {
    int m = blockIdx.x, tid = threadIdx.x;
    const float* lr = logits + (size_t)m * VOCAB;
    __shared__ float red[256];
    float mx = -1e30f;
    for (int n = tid; n < VOCAB; n += 256) mx = fmaxf(mx, lr[n]);
    red[tid] = mx;
    __syncthreads();
    for (int s = 128; s > 0; s >>= 1) {
        if (tid < s) red[tid] = fmaxf(red[tid], red[tid + s]);
        __syncthreads();
    }
    mx = red[0];
    __syncthreads();
    float sum = 0.f;
    for (int n = tid; n < VOCAB; n += 256) sum += __expf(lr[n] - mx);
    red[tid] = sum;
    __syncthreads();
    for (int s = 128; s > 0; s >>= 1) {
        if (tid < s) red[tid] += red[tid + s];
        __syncthreads();
    }
    if (tid == 0)
        nll[m] = (logf(red[0]) + mx) - lr[tgt[m]];
}

__global__ __launch_bounds__(256)
void loss_reduce_kernel(const float* __restrict__ nll, float* __restrict__ out) {
    __shared__ float red[256];
    int tid = threadIdx.x;
    float s = 0.f;
    for (int i = tid; i < MTOK; i += 256) s += nll[i];
    red[tid] = s;
    __syncthreads();
    for (int k = 128; k > 0; k >>= 1) {
        if (tid < k) red[tid] += red[tid + k];
        __syncthreads();
    }
    if (tid == 0) out[0] = red[0] * (1.0f / MTOK);
}

/* ================= host orchestration ==================================== */
extern "C" void kernel_launch(void* const* d_in, const int* in_sizes, int n_in,
                              void* d_out, int out_size) {
    const int*   idx   = (const int*)  d_in[0];
    const int*   tgt   = (const int*)  d_in[1];
    const float* emb   = (const float*)d_in[2];
    const float* wq    = (const float*)d_in[3];
    const float* wk    = (const float*)d_in[4];
    const float* wv    = (const float*)d_in[5];
    const float* wproj = (const float*)d_in[6];
    const float* bproj = (const float*)d_in[7];
    const float* w1    = (const float*)d_in[8];
    const float* b1    = (const float*)d_in[9];
    const float* w2    = (const float*)d_in[10];
    const float* b2    = (const float*)d_in[11];
    const float* ln1g  = (const float*)d_in[12];
    const float* ln1b  = (const float*)d_in[13];
    const float* ln2g  = (const float*)d_in[14];
    const float* ln2b  = (const float*)d_in[15];
    const float* lm_w  = (const float*)d_in[16];
    const float* lm_b  = (const float*)d_in[17];

    float *x, *qkv, *nll, *lscr;
    float2* cs;
    __nv_bfloat16 *yh, *yl, *oh, *ol, *hh, *hl;
    __nv_bfloat16 *qkvTh, *qkvTl, *projTh, *projTl, *w1Th, *w1Tl, *w2Th, *w2Tl, *lmTh, *lmTl;
    cudaGetSymbolAddress((void**)&x,     g_x);
    cudaGetSymbolAddress((void**)&yh,    g_yh);
    cudaGetSymbolAddress((void**)&yl,    g_yl);
    cudaGetSymbolAddress((void**)&qkv,   g_qkv);
    cudaGetSymbolAddress((void**)&oh,    g_oh);
    cudaGetSymbolAddress((void**)&ol,    g_ol);
    cudaGetSymbolAddress((void**)&hh,    g_hh);
    cudaGetSymbolAddress((void**)&hl,    g_hl);
    cudaGetSymbolAddress((void**)&nll,   g_nllv);
    cudaGetSymbolAddress((void**)&lscr,  g_logits_scratch);
    cudaGetSymbolAddress((void**)&cs,    g_cs);
    cudaGetSymbolAddress((void**)&qkvTh, g_qkvT_h);
    cudaGetSymbolAddress((void**)&qkvTl, g_qkvT_l);
    cudaGetSymbolAddress((void**)&projTh, g_projT_h);
    cudaGetSymbolAddress((void**)&projTl, g_projT_l);
    cudaGetSymbolAddress((void**)&w1Th,  g_w1T_h);
    cudaGetSymbolAddress((void**)&w1Tl,  g_w1T_l);
    cudaGetSymbolAddress((void**)&w2Th,  g_w2T_h);
    cudaGetSymbolAddress((void**)&w2Tl,  g_w2T_l);
    cudaGetSymbolAddress((void**)&lmTh,  g_lmT_h);
    cudaGetSymbolAddress((void**)&lmTl,  g_lmT_l);

    cudaFuncSetAttribute(mma_gemm<false, false, false>, cudaFuncAttributeMaxDynamicSharedMemorySize, SMTOT);
    cudaFuncSetAttribute(mma_gemm<false, false, true >, cudaFuncAttributeMaxDynamicSharedMemorySize, SMTOT);
    cudaFuncSetAttribute(mma_gemm<true,  true,  false>, cudaFuncAttributeMaxDynamicSharedMemorySize, SMTOT);

    const long BTV = (long)MTOK * VOCAB;
    float* logits = ((long)out_size >= BTV) ? (float*)d_out : lscr;

    dim3 tb(32, 8);
    /* my launches 0..3; ncu -s 5 lands on my launch #3 = the QKV mma_gemm */
    embed_kernel<<<(MTOK * E_DIM + 255) / 256, 256>>>(idx, emb, x);                    /* 0 */
    wt_qkv_all<<<dim3(2, 32, 288), tb>>>(wq, wk, wv, qkvTh, qkvTl);                    /* 1 */
    ln_split_kernel<<<MTOK, 256>>>(x, ln1g, ln1b, yh, yl);                             /* 2 */
    mma_gemm<false, false, true><<<dim3(3 * E_DIM / 128, MTOK / 128), 256, SMTOT>>>(   /* 3 */
        yh, yl, qkvTh, qkvTl, E_DIM, 3 * E_DIM,
        qkv, nullptr, nullptr, nullptr, nullptr, (const float2*)cs);

    attn_kernel<<<dim3(T_LEN / QG, BATCH * N_HEAD), 256>>>(qkv, oh, ol);

    /* remaining weight transposes */
    wt_gen<<<dim3(32, 32, N_LAYER), tb>>>(wproj, (long)E_DIM * E_DIM, projTh, projTl,
                                          (long)E_DIM * E_DIM, E_DIM, E_DIM);
    wt_gen<<<dim3(128, 32, N_LAYER), tb>>>(w1, (long)E_DIM * FF, w1Th, w1Tl,
                                           (long)E_DIM * FF, E_DIM, FF);
    wt_gen<<<dim3(32, 128, N_LAYER), tb>>>(w2, (long)FF * E_DIM, w2Th, w2Tl,
                                           (long)FF * E_DIM, FF, E_DIM);
    wt_gen<<<dim3(1000, 32, 1), tb>>>(lm_w, 0, lmTh, lmTl, 0, E_DIM, VOCAB);

    for (int l = 0; l < N_LAYER; l++) {
        size_t qkvW = (size_t)l * 3 * E_DIM * E_DIM;
        size_t prW  = (size_t)l * E_DIM * E_DIM;
        size_t w1W  = (size_t)l * FF * E_DIM;

        if (l > 0) {
            ln_split_kernel<<<MTOK, 256>>>(x, ln1g + (size_t)l * E_DIM, ln1b + (size_t)l * E_DIM, yh, yl);
            mma_gemm<false, false, true><<<dim3(3 * E_DIM / 128, MTOK / 128), 256, SMTOT>>>(
                yh, yl, qkvTh + qkvW, qkvTl + qkvW, E_DIM, 3 * E_DIM,
                qkv, nullptr, nullptr, nullptr, nullptr, (const float2*)cs);
            attn_kernel<<<dim3(T_LEN / QG, BATCH * N_HEAD), 256>>>(qkv, oh, ol);
        }

        mma_gemm<false, false, false><<<dim3(E_DIM / 128, MTOK / 128), 256, SMTOT>>>(
            oh, ol, projTh + prW, projTl + prW, E_DIM, E_DIM,
            x, nullptr, nullptr, bproj + (size_t)l * E_DIM, x, nullptr);

        ln_split_kernel<<<MTOK, 256>>>(x, ln2g + (size_t)l * E_DIM, ln2b + (size_t)l * E_DIM, yh, yl);

        mma_gemm<true, true, false><<<dim3(FF / 128, MTOK / 128), 256, SMTOT>>>(
            yh, yl, w1Th + w1W, w1Tl + w1W, E_DIM, FF,
            nullptr, hh, hl, b1 + (size_t)l * FF, nullptr, nullptr);

        mma_gemm<false, false, false><<<dim3(E_DIM / 128, MTOK / 128), 256, SMTOT>>>(
            hh, hl, w2Th + w1W, w2Tl + w1W, FF, E_DIM,
            x, nullptr, nullptr, b2 + (size_t)l * E_DIM, x, nullptr);
    }

    split_kernel<<<(MTOK * E_DIM + 255) / 256, 256>>>(x, yh, yl, MTOK * E_DIM);

    mma_gemm<false, false, false><<<dim3(VOCAB / 128, MTOK / 128), 256, SMTOT>>>(
        yh, yl, lmTh, lmTl, E_DIM, VOCAB,
        logits, nullptr, nullptr, lm_b, nullptr, nullptr);

    nll_kernel<<<MTOK, 256>>>(logits, tgt, nll);

    if ((long)out_size == BTV + 1) {
        loss_reduce_kernel<<<1, 256>>>(nll, (float*)d_out + BTV);
    } else if ((long)out_size < BTV) {
        loss_reduce_kernel<<<1, 256>>>(nll, (float*)d_out);
    }
}